// round 14
// baseline (speedup 1.0000x reference)
#include <cuda_runtime.h>
#include <math.h>
#include <stdint.h>

#define Bc 4
#define Tc 1024
#define Dc 1024
#define Hc 16
#define HSc 64
#define Lc 2047

__device__ float g_q[Bc * Tc * Dc];
__device__ float g_k[Bc * Tc * Dc];
__device__ float g_v[Bc * Tc * Dc];
__device__ float g_p[Lc * Dc];
__device__ float g_ctx[Bc * Tc * Dc];

__device__ __forceinline__ uint32_t tf32_of(float x) {
    uint32_t r;
    asm("cvt.rna.tf32.f32 %0, %1;" : "=r"(r) : "f"(x));
    return r;
}
__device__ __forceinline__ void mma_p(float* d, uint4 a, uint2 b) {
    asm volatile(
        "mma.sync.aligned.m16n8k8.row.col.f32.tf32.tf32.f32 "
        "{%0,%1,%2,%3},{%4,%5,%6,%7},{%8,%9},{%0,%1,%2,%3};"
        : "+f"(d[0]), "+f"(d[1]), "+f"(d[2]), "+f"(d[3])
        : "r"(a.x), "r"(a.y), "r"(a.z), "r"(a.w), "r"(b.x), "r"(b.y));
}

// FMA-pipe exp: 2^y via magic-round + degree-5 poly.
__device__ __forceinline__ float fexp2(float y) {
    y = fmaxf(y, -100.f);
    float rn = y + 12582912.f;
    int n = __float_as_int(rn) - 0x4B400000;
    float f = y - (rn - 12582912.f);
    float p = 1.3333558e-3f;
    p = fmaf(p, f, 9.6181290e-3f);
    p = fmaf(p, f, 5.5504108e-2f);
    p = fmaf(p, f, 2.4022650e-1f);
    p = fmaf(p, f, 6.9314718e-1f);
    p = fmaf(p, f, 1.0f);
    return __int_as_float(__float_as_int(p) + (n << 23));
}
#define EXP_SCALE 0.18033688011112042f   /* 0.125 * log2(e) */

// ---- packed A fragments ----
template <int RB>
__device__ __forceinline__ void storeA(uint32_t* sA, int oct, int r, const float* f) {
    uint32_t* b = sA + oct * (RB * 128 + 8) + (r >> 4) * 128 + (r & 7) * 16 + ((r >> 3) & 1);
    int gs = r & 3;
#pragma unroll
    for (int p = 0; p < 4; p++) {
        int tq = p ^ gs;
        b[p * 4] = tf32_of(f[tq]);
        b[p * 4 + 2] = tf32_of(f[tq + 4]);
    }
}
template <int RB>
__device__ __forceinline__ uint4 loadA(const uint32_t* sA, int oct, int rb, int gid, int tig) {
    return *(const uint4*)(sA + oct * (RB * 128 + 8) + rb * 128 + gid * 16 +
                           ((tig ^ (gid & 3)) << 2));
}
// ---- packed B fragments ----
template <int S>
__device__ __forceinline__ void storeB(uint32_t* sB, int oct, int c, const float* f) {
    uint32_t* b = sB + oct * (S * 8 + 8) + c * 2;
#pragma unroll
    for (int tq = 0; tq < 4; tq++)
        *(uint2*)(b + tq * S * 2) = make_uint2(tf32_of(f[tq]), tf32_of(f[tq + 4]));
}
template <int S>
__device__ __forceinline__ uint2 loadB(const uint32_t* sB, int oct, int tig, int c) {
    return *(const uint2*)(sB + oct * (S * 8 + 8) + (tig * S + c) * 2);
}

__device__ __forceinline__ void ld8(const float* p, bool ok, float* f) {
    float4 z = make_float4(0.f, 0.f, 0.f, 0.f);
    float4 x0 = ok ? *(const float4*)p : z;
    float4 x1 = ok ? *(const float4*)(p + 4) : z;
    f[0] = x0.x; f[1] = x0.y; f[2] = x0.z; f[3] = x0.w;
    f[4] = x1.x; f[5] = x1.y; f[6] = x1.z; f[7] = x1.w;
}

// ============================================================
// GEMM body (unchanged, proven)
// ============================================================
__device__ __forceinline__ void gemm_body(const float* __restrict__ A,
                                          const float* __restrict__ W,
                                          const float* __restrict__ bias,
                                          float* __restrict__ C,
                                          int M, int N, int K, int m0, int n0) {
    __shared__ __align__(16) uint32_t sA[2][2 * (8 * 128 + 8)];
    __shared__ __align__(16) uint32_t sB[2][2 * (132 * 8 + 8)];
    const int tid = threadIdx.x;
    const int lrow = tid >> 1, oct = tid & 1, lk = oct * 8;
    const int lane = tid & 31, wid = tid >> 5;
    const int rb0 = (wid >> 1) * 2, nB = (wid & 1) * 64;
    const int gid = lane >> 2, tig = lane & 3;

    float acc[2][8][4];
#pragma unroll
    for (int i = 0; i < 2; i++)
#pragma unroll
        for (int j = 0; j < 8; j++)
#pragma unroll
            for (int c = 0; c < 4; c++) acc[i][j][c] = 0.f;

    const bool av = (m0 + lrow) < M, wv = (n0 + lrow) < N;
    const float* Ar = A + (size_t)(m0 + lrow) * K + lk;
    const float* Wr = W + (size_t)(n0 + lrow) * K + lk;
    float fA[8], fB[8];
    ld8(Ar, av, fA);
    ld8(Wr, wv, fB);
    storeA<8>(sA[0], oct, lrow, fA);
    storeB<132>(sB[0], oct, lrow, fB);
    __syncthreads();

    const int nk = K / 16;
    for (int kt = 0; kt < nk; kt++) {
        const int cur = kt & 1;
        const bool more = (kt + 1) < nk;
        if (more) {
            ld8(Ar + (kt + 1) * 16, av, fA);
            ld8(Wr + (kt + 1) * 16, wv, fB);
        }
#pragma unroll
        for (int o = 0; o < 2; o++) {
            uint4 a0 = loadA<8>(sA[cur], o, rb0, gid, tig);
            uint4 a1 = loadA<8>(sA[cur], o, rb0 + 1, gid, tig);
#pragma unroll
            for (int nt = 0; nt < 8; nt++) {
                uint2 bv = loadB<132>(sB[cur], o, tig, nB + nt * 8 + gid);
                mma_p(acc[0][nt], a0, bv);
                mma_p(acc[1][nt], a1, bv);
            }
        }
        if (more) {
            storeA<8>(sA[cur ^ 1], oct, lrow, fA);
            storeB<132>(sB[cur ^ 1], oct, lrow, fB);
            __syncthreads();
        }
    }

#pragma unroll
    for (int mt = 0; mt < 2; mt++) {
        int r = m0 + (rb0 + mt) * 16 + gid;
#pragma unroll
        for (int nt = 0; nt < 8; nt++) {
            int c = n0 + nB + nt * 8 + 2 * tig;
            float b0v = bias ? bias[c] : 0.f;
            float b1v = bias ? bias[c + 1] : 0.f;
            if (r < M)
                *(float2*)(C + (size_t)r * N + c) =
                    make_float2(acc[mt][nt][0] + b0v, acc[mt][nt][1] + b1v);
            if (r + 8 < M)
                *(float2*)(C + (size_t)(r + 8) * N + c) =
                    make_float2(acc[mt][nt][2] + b0v, acc[mt][nt][3] + b1v);
        }
    }
}

__global__ __launch_bounds__(256, 2) void gemm_tc_nt(
    const float* __restrict__ A, const float* __restrict__ W,
    const float* __restrict__ bias, float* __restrict__ C, int M, int N, int K) {
    gemm_body(A, W, bias, C, M, N, K, blockIdx.y * 128, blockIdx.x * 128);
}

__global__ __launch_bounds__(256, 2) void gemm_qkvp(
    const float* __restrict__ A, const float* __restrict__ rpe,
    const float* __restrict__ Wq, const float* __restrict__ Wk, const float* __restrict__ Wv,
    const float* __restrict__ Wp,
    const float* __restrict__ bq, const float* __restrict__ bk, const float* __restrict__ bv,
    float* __restrict__ Cq, float* __restrict__ Ck, float* __restrict__ Cv,
    float* __restrict__ Cp) {
    const int sel = blockIdx.x >> 3;
    if (sel == 3) {
        if (blockIdx.y >= 16) return;
        gemm_body(rpe, Wp, nullptr, Cp, Lc, Dc, Dc, blockIdx.y * 128, (blockIdx.x & 7) * 128);
        return;
    }
    const float* W = (sel == 0) ? Wq : (sel == 1) ? Wk : Wv;
    const float* bias = (sel == 0) ? bq : (sel == 1) ? bk : bv;
    float* C = (sel == 0) ? Cq : (sel == 1) ? Ck : Cv;
    gemm_body(A, W, bias, C, Bc * Tc, Dc, Dc, blockIdx.y * 128, (blockIdx.x & 7) * 128);
}

// ============================================================
// FUSED attention per (bh, 32-row q tile) — 512 threads, depth-2
// register prefetch (LDG window = 2 strips), double-buffered smem.
// smem (u32): Sb 32*1028 | Au 8*264 | Av 8*264 | Bf 2*4608 | mx 32 | inv 32
// ============================================================
#define SB_STR 1028
#define AU_OFF (32 * SB_STR)
#define AV_OFF (AU_OFF + 8 * 264)
#define BF_OFF (AV_OFF + 8 * 264)
#define BF_STR 4608
#define MX_OFF (BF_OFF + 2 * BF_STR)
#define INV_OFF (MX_OFF + 32)
#define FUSED_SMEM_BYTES ((INV_OFF + 32) * 4)

__global__ __launch_bounds__(512, 1) void fused_attn(
    const float* __restrict__ Q, const float* __restrict__ K,
    const float* __restrict__ P, const float* __restrict__ V,
    const float* __restrict__ u, const float* __restrict__ vb,
    float* __restrict__ probs, float* __restrict__ ctx) {
    extern __shared__ __align__(16) uint32_t su[];
    float* Sb = (float*)su;
    uint32_t* Au = su + AU_OFF;
    uint32_t* Av = su + AV_OFF;
    uint32_t* Bf = su + BF_OFF;
    float* mx_s = (float*)(su + MX_OFF);
    float* inv_s = (float*)(su + INV_OFF);

    const int t = threadIdx.x;
    const int bh = blockIdx.y, zb = bh >> 4, h = bh & 15;
    const int q0 = blockIdx.x * 32;
    const int lane = t & 31, w = t >> 5;
    const int mB = (w & 1) * 16, rbw = w & 1, nBf = (w >> 1) * 8;
    const int gid = lane >> 2, tig = lane & 3;

    // ---- stage q+u (t<256) / q+v (t>=256) as packed A fragments ----
    {
        int tt = t & 255;
        int qr = tt >> 3, o = tt & 7;
        const float* qp = Q + ((size_t)(zb * Tc) + q0 + qr) * Dc + h * HSc + o * 8;
        float a[8], bb[8];
        ld8(qp, true, a);
        if (t < 256) {
            ld8(u + h * HSc + o * 8, true, bb);
#pragma unroll
            for (int i = 0; i < 8; i++) bb[i] += a[i];
            storeA<2>(Au, o, qr, bb);
        } else {
            ld8(vb + h * HSc + o * 8, true, bb);
#pragma unroll
            for (int i = 0; i < 8; i++) bb[i] += a[i];
            storeA<2>(Av, o, qr, bb);
        }
    }

    const int kr = t >> 3, oc8 = t & 7;
    float fr[2][8];
    uint4 aF[8];
    const float* Kbase = K + ((size_t)(zb * Tc) + kr) * Dc + h * HSc + oc8 * 8;
    const size_t Kstep = (size_t)64 * Dc;

    // ================= phase 1: ac = (q+u) K^T =================
    ld8(Kbase, true, fr[0]);
    storeB<68>(Bf, oc8, kr, fr[0]);
    ld8(Kbase + Kstep, true, fr[1]);          // strip 1
    ld8(Kbase + 2 * Kstep, true, fr[0]);      // strip 2 (slot 0 free after store)
    __syncthreads();
#pragma unroll
    for (int o = 0; o < 8; o++) aF[o] = loadA<2>(Au, o, rbw, gid, tig);
    for (int s = 0; s < 16; s++) {
        const uint32_t* bufc = Bf + (s & 1) * BF_STR;
        if (s + 1 < 16) {
            int slot = (s + 1) & 1;
            storeB<68>(Bf + slot * BF_STR, oc8, kr, fr[slot]);
            if (s + 3 < 16) ld8(Kbase + (size_t)(s + 3) * Kstep, true, fr[slot]);
        }
        float acc[4] = {0.f, 0.f, 0.f, 0.f};
#pragma unroll
        for (int o = 0; o < 8; o++)
            mma_p(acc, aF[o], loadB<68>(bufc, o, tig, nBf + gid));
        int col = s * 64 + nBf + 2 * tig;
        *(float2*)&Sb[(mB + gid) * SB_STR + col] = make_float2(acc[0], acc[1]);
        *(float2*)&Sb[(mB + gid + 8) * SB_STR + col] = make_float2(acc[2], acc[3]);
        __syncthreads();
    }

    // ================= phase 2: bd band, scatter-add =================
    const int lStart = (Tc - 1) - (q0 + 31);
#pragma unroll
    for (int o = 0; o < 8; o++) aF[o] = loadA<2>(Av, o, rbw, gid, tig);
    {
        int l0 = lStart + kr;
        if (l0 < Lc) ld8(P + (size_t)l0 * Dc + h * HSc + oc8 * 8, true, fr[0]);
        else {
#pragma unroll
            for (int i = 0; i < 8; i++) fr[0][i] = 0.f;
        }
        storeB<68>(Bf, oc8, kr, fr[0]);
        int l1 = lStart + 64 + kr;
        if (l1 < Lc) ld8(P + (size_t)l1 * Dc + h * HSc + oc8 * 8, true, fr[1]);
        else {
#pragma unroll
            for (int i = 0; i < 8; i++) fr[1][i] = 0.f;
        }
        int l2 = lStart + 128 + kr;
        if (l2 < Lc) ld8(P + (size_t)l2 * Dc + h * HSc + oc8 * 8, true, fr[0]);
        else {
#pragma unroll
            for (int i = 0; i < 8; i++) fr[0][i] = 0.f;
        }
    }
    __syncthreads();
    for (int s = 0; s < 17; s++) {
        int lBase = lStart + s * 64;
        const uint32_t* bufc = Bf + (s & 1) * BF_STR;
        if (s + 1 < 17) {
            int slot = (s + 1) & 1;
            storeB<68>(Bf + slot * BF_STR, oc8, kr, fr[slot]);
            if (s + 3 < 17) {
                int l = lStart + (s + 3) * 64 + kr;
                if (l < Lc) ld8(P + (size_t)l * Dc + h * HSc + oc8 * 8, true, fr[slot]);
                else {
#pragma unroll
                    for (int i = 0; i < 8; i++) fr[slot][i] = 0.f;
                }
            }
        }
        float acc[4] = {0.f, 0.f, 0.f, 0.f};
#pragma unroll
        for (int o = 0; o < 8; o++)
            mma_p(acc, aF[o], loadB<68>(bufc, o, tig, nBf + gid));
        int lc = lBase + nBf + 2 * tig;
        int m = mB + gid;
        int j = (q0 + m) + lc - (Tc - 1);
        if (j >= 0 && j < Tc) Sb[m * SB_STR + j] += acc[0];
        if (j + 1 >= 0 && j + 1 < Tc) Sb[m * SB_STR + j + 1] += acc[1];
        int j2 = j + 8;
        if (j2 >= 0 && j2 < Tc) Sb[(m + 8) * SB_STR + j2] += acc[2];
        if (j2 + 1 >= 0 && j2 + 1 < Tc) Sb[(m + 8) * SB_STR + j2 + 1] += acc[3];
        __syncthreads();
    }

    // ===== phase 3a: row max (2 rows/warp) =====
#pragma unroll
    for (int rr = 0; rr < 2; rr++) {
        int row_i = w * 2 + rr;
        const float* row = Sb + row_i * SB_STR;
        float mx = -3.4e38f;
        for (int c = lane; c < Tc; c += 32) mx = fmaxf(mx, row[c]);
#pragma unroll
        for (int o = 16; o; o >>= 1) mx = fmaxf(mx, __shfl_xor_sync(0xffffffffu, mx, o));
        if (lane == 0) mx_s[row_i] = mx;
    }
    __syncthreads();

    // ===== phase 4: exp (FMA) + ctx, depth-2 prefetch =====
    const int row_e = t >> 4;
    const int ce = (t & 15) * 4;
    const float mxc = mx_s[row_e] * EXP_SCALE;
    float psum = 0.f;
    float* erow = Sb + row_e * SB_STR;

    {   // exp strip 0
        float4 x0 = *(float4*)&erow[ce];
        x0.x = fexp2(fmaf(x0.x, EXP_SCALE, -mxc)); x0.y = fexp2(fmaf(x0.y, EXP_SCALE, -mxc));
        x0.z = fexp2(fmaf(x0.z, EXP_SCALE, -mxc)); x0.w = fexp2(fmaf(x0.w, EXP_SCALE, -mxc));
        *(float4*)&erow[ce] = x0;
        psum += x0.x + x0.y + x0.z + x0.w;
    }

    float acc2[4] = {0.f, 0.f, 0.f, 0.f};
    const float* Vbase = V + ((size_t)(zb * Tc) + kr) * Dc + h * HSc + oc8 * 8;
    ld8(Vbase, true, fr[0]);
    {
        uint32_t* dst = Bf + kr * 72 + oc8 * 8;
        *(uint4*)(dst + 0) = make_uint4(tf32_of(fr[0][0]), tf32_of(fr[0][1]),
                                        tf32_of(fr[0][2]), tf32_of(fr[0][3]));
        *(uint4*)(dst + 4) = make_uint4(tf32_of(fr[0][4]), tf32_of(fr[0][5]),
                                        tf32_of(fr[0][6]), tf32_of(fr[0][7]));
    }
    ld8(Vbase + Kstep, true, fr[1]);
    ld8(Vbase + 2 * Kstep, true, fr[0]);
    __syncthreads();
    for (int s = 0; s < 16; s++) {
        const uint32_t* Vtc = Bf + (s & 1) * BF_STR;
        if (s + 1 < 16) {
            int slot = (s + 1) & 1;
            uint32_t* dst = Bf + slot * BF_STR + kr * 72 + oc8 * 8;
            *(uint4*)(dst + 0) = make_uint4(tf32_of(fr[slot][0]), tf32_of(fr[slot][1]),
                                            tf32_of(fr[slot][2]), tf32_of(fr[slot][3]));
            *(uint4*)(dst + 4) = make_uint4(tf32_of(fr[slot][4]), tf32_of(fr[slot][5]),
                                            tf32_of(fr[slot][6]), tf32_of(fr[slot][7]));
            if (s + 3 < 16) ld8(Vbase + (size_t)(s + 3) * Kstep, true, fr[slot]);
            float* ep = erow + (s + 1) * 64 + ce;
            float4 x0 = *(float4*)ep;
            x0.x = fexp2(fmaf(x0.x, EXP_SCALE, -mxc)); x0.y = fexp2(fmaf(x0.y, EXP_SCALE, -mxc));
            x0.z = fexp2(fmaf(x0.z, EXP_SCALE, -mxc)); x0.w = fexp2(fmaf(x0.w, EXP_SCALE, -mxc));
            *(float4*)ep = x0;
            psum += x0.x + x0.y + x0.z + x0.w;
        }

        const float* ar0 = Sb + (mB + gid) * SB_STR + s * 64;
        const float* ar8 = ar0 + 8 * SB_STR;
#pragma unroll
        for (int o = 0; o < 8; o++) {
            uint4 a;
            a.x = tf32_of(ar0[o * 8 + tig]);
            a.y = tf32_of(ar8[o * 8 + tig]);
            a.z = tf32_of(ar0[o * 8 + tig + 4]);
            a.w = tf32_of(ar8[o * 8 + tig + 4]);
            int c = nBf + gid;
            uint2 b;
            b.x = Vtc[(o * 8 + tig) * 72 + c];
            b.y = Vtc[(o * 8 + tig + 4) * 72 + c];
            mma_p(acc2, a, b);
        }
        __syncthreads();
    }

    // ---- row-sum reduce over 16 lanes sharing a row ----
#pragma unroll
    for (int o = 8; o; o >>= 1) psum += __shfl_xor_sync(0xffffffffu, psum, o);
    if ((lane & 15) == 0) inv_s[row_e] = 1.f / psum;
    __syncthreads();

    // ---- write probs = e * inv ----
    {
        float* pb = probs + ((size_t)bh << 20) + (size_t)q0 * Tc;
#pragma unroll 4
        for (int it = 0; it < 16; it++) {
            int idx = it * 512 + t;
            int r = idx >> 8, c4 = (idx & 255) * 4;
            float iv = inv_s[r];
            float4 val = *(float4*)&Sb[r * SB_STR + c4];
            val.x *= iv; val.y *= iv; val.z *= iv; val.w *= iv;
            *(float4*)(pb + (size_t)r * Tc + c4) = val;
        }
    }

    // ---- ctx epilogue: scale by inv ----
    {
        int r = q0 + mB + gid;
        float iv0 = inv_s[mB + gid], iv8 = inv_s[mB + gid + 8];
        int c = nBf + 2 * tig;
        *(float2*)(ctx + ((size_t)(zb * Tc) + r) * Dc + h * HSc + c) =
            make_float2(acc2[0] * iv0, acc2[1] * iv0);
        *(float2*)(ctx + ((size_t)(zb * Tc) + r + 8) * Dc + h * HSc + c) =
            make_float2(acc2[2] * iv8, acc2[3] * iv8);
    }
}

// ============================================================
extern "C" void kernel_launch(void* const* d_in, const int* in_sizes, int n_in,
                              void* d_out, int out_size) {
    const float* hs  = (const float*)d_in[0];
    const float* rpe = (const float*)d_in[1];
    const float* Wq  = (const float*)d_in[2];
    const float* bq  = (const float*)d_in[3];
    const float* Wk  = (const float*)d_in[4];
    const float* bk  = (const float*)d_in[5];
    const float* Wv  = (const float*)d_in[6];
    const float* bv  = (const float*)d_in[7];
    const float* Wo  = (const float*)d_in[8];
    const float* bo  = (const float*)d_in[9];
    const float* Wp  = (const float*)d_in[10];
    const float* pu  = (const float*)d_in[11];
    const float* pvb = (const float*)d_in[12];

    float* out = (float*)d_out;
    float* S   = out + (size_t)Bc * Tc * Dc;

    float *pq, *pk, *pv, *pp, *pctx;
    cudaGetSymbolAddress((void**)&pq,   g_q);
    cudaGetSymbolAddress((void**)&pk,   g_k);
    cudaGetSymbolAddress((void**)&pv,   g_v);
    cudaGetSymbolAddress((void**)&pp,   g_p);
    cudaGetSymbolAddress((void**)&pctx, g_ctx);

    cudaFuncSetAttribute(fused_attn, cudaFuncAttributeMaxDynamicSharedMemorySize,
                         FUSED_SMEM_BYTES);

    gemm_qkvp<<<dim3(32, 32), 256>>>(hs, rpe, Wq, Wk, Wv, Wp, bq, bk, bv,
                                     pq, pk, pv, pp);

    fused_attn<<<dim3(Tc / 32, Bc * Hc), 512, FUSED_SMEM_BYTES>>>(
        pq, pk, pp, pv, pu, pvb, S, pctx);

    gemm_tc_nt<<<dim3(8, 32), 256>>>(pctx, Wo, bo, out, Bc * Tc, Dc, Dc);
}

// round 15
// speedup vs baseline: 1.1370x; 1.1370x over previous
#include <cuda_runtime.h>
#include <math.h>
#include <stdint.h>

#define Bc 4
#define Tc 1024
#define Dc 1024
#define Hc 16
#define HSc 64
#define Lc 2047

__device__ float g_q[Bc * Tc * Dc];
__device__ float g_k[Bc * Tc * Dc];
__device__ float g_v[Bc * Tc * Dc];
__device__ float g_p[Lc * Dc];
__device__ float g_ctx[Bc * Tc * Dc];

__device__ __forceinline__ uint32_t tf32_of(float x) {
    uint32_t r;
    asm("cvt.rna.tf32.f32 %0, %1;" : "=r"(r) : "f"(x));
    return r;
}
__device__ __forceinline__ void mma_p(float* d, uint4 a, uint2 b) {
    asm volatile(
        "mma.sync.aligned.m16n8k8.row.col.f32.tf32.tf32.f32 "
        "{%0,%1,%2,%3},{%4,%5,%6,%7},{%8,%9},{%0,%1,%2,%3};"
        : "+f"(d[0]), "+f"(d[1]), "+f"(d[2]), "+f"(d[3])
        : "r"(a.x), "r"(a.y), "r"(a.z), "r"(a.w), "r"(b.x), "r"(b.y));
}

// FMA-pipe exp: 2^y via magic-round + degree-5 poly.
__device__ __forceinline__ float fexp2(float y) {
    y = fmaxf(y, -100.f);
    float rn = y + 12582912.f;
    int n = __float_as_int(rn) - 0x4B400000;
    float f = y - (rn - 12582912.f);
    float p = 1.3333558e-3f;
    p = fmaf(p, f, 9.6181290e-3f);
    p = fmaf(p, f, 5.5504108e-2f);
    p = fmaf(p, f, 2.4022650e-1f);
    p = fmaf(p, f, 6.9314718e-1f);
    p = fmaf(p, f, 1.0f);
    return __int_as_float(__float_as_int(p) + (n << 23));
}
#define EXP_SCALE 0.18033688011112042f   /* 0.125 * log2(e) */

// ---- packed A fragments ----
template <int RB>
__device__ __forceinline__ void storeA(uint32_t* sA, int oct, int r, const float* f) {
    uint32_t* b = sA + oct * (RB * 128 + 8) + (r >> 4) * 128 + (r & 7) * 16 + ((r >> 3) & 1);
    int gs = r & 3;
#pragma unroll
    for (int p = 0; p < 4; p++) {
        int tq = p ^ gs;
        b[p * 4] = tf32_of(f[tq]);
        b[p * 4 + 2] = tf32_of(f[tq + 4]);
    }
}
template <int RB>
__device__ __forceinline__ uint4 loadA(const uint32_t* sA, int oct, int rb, int gid, int tig) {
    return *(const uint4*)(sA + oct * (RB * 128 + 8) + rb * 128 + gid * 16 +
                           ((tig ^ (gid & 3)) << 2));
}
// ---- packed B fragments ----
template <int S>
__device__ __forceinline__ void storeB(uint32_t* sB, int oct, int c, const float* f) {
    uint32_t* b = sB + oct * (S * 8 + 8) + c * 2;
#pragma unroll
    for (int tq = 0; tq < 4; tq++)
        *(uint2*)(b + tq * S * 2) = make_uint2(tf32_of(f[tq]), tf32_of(f[tq + 4]));
}
template <int S>
__device__ __forceinline__ uint2 loadB(const uint32_t* sB, int oct, int tig, int c) {
    return *(const uint2*)(sB + oct * (S * 8 + 8) + (tig * S + c) * 2);
}

__device__ __forceinline__ void ld8(const float* p, bool ok, float* f) {
    float4 z = make_float4(0.f, 0.f, 0.f, 0.f);
    float4 x0 = ok ? *(const float4*)p : z;
    float4 x1 = ok ? *(const float4*)(p + 4) : z;
    f[0] = x0.x; f[1] = x0.y; f[2] = x0.z; f[3] = x0.w;
    f[4] = x1.x; f[5] = x1.y; f[6] = x1.z; f[7] = x1.w;
}

// ============================================================
// GEMM body (unchanged, proven)
// ============================================================
__device__ __forceinline__ void gemm_body(const float* __restrict__ A,
                                          const float* __restrict__ W,
                                          const float* __restrict__ bias,
                                          float* __restrict__ C,
                                          int M, int N, int K, int m0, int n0) {
    __shared__ __align__(16) uint32_t sA[2][2 * (8 * 128 + 8)];
    __shared__ __align__(16) uint32_t sB[2][2 * (132 * 8 + 8)];
    const int tid = threadIdx.x;
    const int lrow = tid >> 1, oct = tid & 1, lk = oct * 8;
    const int lane = tid & 31, wid = tid >> 5;
    const int rb0 = (wid >> 1) * 2, nB = (wid & 1) * 64;
    const int gid = lane >> 2, tig = lane & 3;

    float acc[2][8][4];
#pragma unroll
    for (int i = 0; i < 2; i++)
#pragma unroll
        for (int j = 0; j < 8; j++)
#pragma unroll
            for (int c = 0; c < 4; c++) acc[i][j][c] = 0.f;

    const bool av = (m0 + lrow) < M, wv = (n0 + lrow) < N;
    const float* Ar = A + (size_t)(m0 + lrow) * K + lk;
    const float* Wr = W + (size_t)(n0 + lrow) * K + lk;
    float fA[8], fB[8];
    ld8(Ar, av, fA);
    ld8(Wr, wv, fB);
    storeA<8>(sA[0], oct, lrow, fA);
    storeB<132>(sB[0], oct, lrow, fB);
    __syncthreads();

    const int nk = K / 16;
    for (int kt = 0; kt < nk; kt++) {
        const int cur = kt & 1;
        const bool more = (kt + 1) < nk;
        if (more) {
            ld8(Ar + (kt + 1) * 16, av, fA);
            ld8(Wr + (kt + 1) * 16, wv, fB);
        }
#pragma unroll
        for (int o = 0; o < 2; o++) {
            uint4 a0 = loadA<8>(sA[cur], o, rb0, gid, tig);
            uint4 a1 = loadA<8>(sA[cur], o, rb0 + 1, gid, tig);
#pragma unroll
            for (int nt = 0; nt < 8; nt++) {
                uint2 bv = loadB<132>(sB[cur], o, tig, nB + nt * 8 + gid);
                mma_p(acc[0][nt], a0, bv);
                mma_p(acc[1][nt], a1, bv);
            }
        }
        if (more) {
            storeA<8>(sA[cur ^ 1], oct, lrow, fA);
            storeB<132>(sB[cur ^ 1], oct, lrow, fB);
            __syncthreads();
        }
    }

#pragma unroll
    for (int mt = 0; mt < 2; mt++) {
        int r = m0 + (rb0 + mt) * 16 + gid;
#pragma unroll
        for (int nt = 0; nt < 8; nt++) {
            int c = n0 + nB + nt * 8 + 2 * tig;
            float b0v = bias ? bias[c] : 0.f;
            float b1v = bias ? bias[c + 1] : 0.f;
            if (r < M)
                *(float2*)(C + (size_t)r * N + c) =
                    make_float2(acc[mt][nt][0] + b0v, acc[mt][nt][1] + b1v);
            if (r + 8 < M)
                *(float2*)(C + (size_t)(r + 8) * N + c) =
                    make_float2(acc[mt][nt][2] + b0v, acc[mt][nt][3] + b1v);
        }
    }
}

__global__ __launch_bounds__(256, 2) void gemm_tc_nt(
    const float* __restrict__ A, const float* __restrict__ W,
    const float* __restrict__ bias, float* __restrict__ C, int M, int N, int K) {
    gemm_body(A, W, bias, C, M, N, K, blockIdx.y * 128, blockIdx.x * 128);
}

__global__ __launch_bounds__(256, 2) void gemm_qkvp(
    const float* __restrict__ A, const float* __restrict__ rpe,
    const float* __restrict__ Wq, const float* __restrict__ Wk, const float* __restrict__ Wv,
    const float* __restrict__ Wp,
    const float* __restrict__ bq, const float* __restrict__ bk, const float* __restrict__ bv,
    float* __restrict__ Cq, float* __restrict__ Ck, float* __restrict__ Cv,
    float* __restrict__ Cp) {
    const int sel = blockIdx.x >> 3;
    if (sel == 3) {
        if (blockIdx.y >= 16) return;
        gemm_body(rpe, Wp, nullptr, Cp, Lc, Dc, Dc, blockIdx.y * 128, (blockIdx.x & 7) * 128);
        return;
    }
    const float* W = (sel == 0) ? Wq : (sel == 1) ? Wk : Wv;
    const float* bias = (sel == 0) ? bq : (sel == 1) ? bk : bv;
    float* C = (sel == 0) ? Cq : (sel == 1) ? Ck : Cv;
    gemm_body(A, W, bias, C, Bc * Tc, Dc, Dc, blockIdx.y * 128, (blockIdx.x & 7) * 128);
}

// ============================================================
// FUSED attention per (bh, 32-row q tile) — 512 threads, 128-wide
// strips (half the barriers, 2x prefetch window), FMA exp.
// smem (u32): Sb 32*1028 | Au 8*264 | Av 8*264 | Bf 2*9216 | mx 32 | inv 32
// ============================================================
#define SB_STR 1028
#define AU_OFF (32 * SB_STR)
#define AV_OFF (AU_OFF + 8 * 264)
#define BF_OFF (AV_OFF + 8 * 264)
#define BF_STR 9216
#define MX_OFF (BF_OFF + 2 * BF_STR)
#define INV_OFF (MX_OFF + 32)
#define FUSED_SMEM_BYTES ((INV_OFF + 32) * 4)

__global__ __launch_bounds__(512, 1) void fused_attn(
    const float* __restrict__ Q, const float* __restrict__ K,
    const float* __restrict__ P, const float* __restrict__ V,
    const float* __restrict__ u, const float* __restrict__ vb,
    float* __restrict__ probs, float* __restrict__ ctx) {
    extern __shared__ __align__(16) uint32_t su[];
    float* Sb = (float*)su;
    uint32_t* Au = su + AU_OFF;
    uint32_t* Av = su + AV_OFF;
    uint32_t* Bf = su + BF_OFF;
    float* mx_s = (float*)(su + MX_OFF);
    float* inv_s = (float*)(su + INV_OFF);

    const int t = threadIdx.x;
    const int bh = blockIdx.y, zb = bh >> 4, h = bh & 15;
    const int q0 = blockIdx.x * 32;
    const int lane = t & 31, w = t >> 5;
    const int mB = (w & 1) * 16, rbw = w & 1, nBf = (w >> 1) * 8;
    const int gid = lane >> 2, tig = lane & 3;

    // ---- stage q+u (t<256) / q+v (t>=256) as packed A fragments ----
    {
        int tt = t & 255;
        int qr = tt >> 3, o = tt & 7;
        const float* qp = Q + ((size_t)(zb * Tc) + q0 + qr) * Dc + h * HSc + o * 8;
        float a[8], bb[8];
        ld8(qp, true, a);
        if (t < 256) {
            ld8(u + h * HSc + o * 8, true, bb);
#pragma unroll
            for (int i = 0; i < 8; i++) bb[i] += a[i];
            storeA<2>(Au, o, qr, bb);
        } else {
            ld8(vb + h * HSc + o * 8, true, bb);
#pragma unroll
            for (int i = 0; i < 8; i++) bb[i] += a[i];
            storeA<2>(Av, o, qr, bb);
        }
    }

    const int kr = t >> 3, oc8 = t & 7;   // staging: rows kr and kr+64, oct oc8
    float f0[8], f1[8];
    uint4 aF[8];
    const float* Kbase = K + ((size_t)(zb * Tc) + kr) * Dc + h * HSc + oc8 * 8;
    const size_t R64 = (size_t)64 * Dc;

    // ================= phase 1: ac = (q+u) K^T, 8 strips x 128 =================
    ld8(Kbase, true, f0);
    ld8(Kbase + R64, true, f1);
    storeB<132>(Bf, oc8, kr, f0);
    storeB<132>(Bf, oc8, kr + 64, f1);
    __syncthreads();
#pragma unroll
    for (int o = 0; o < 8; o++) aF[o] = loadA<2>(Au, o, rbw, gid, tig);
    ld8(Kbase + 2 * R64, true, f0);
    ld8(Kbase + 3 * R64, true, f1);
    for (int s = 0; s < 8; s++) {
        const uint32_t* bufc = Bf + (s & 1) * BF_STR;
        if (s + 1 < 8) {
            uint32_t* bufn = Bf + ((s + 1) & 1) * BF_STR;
            storeB<132>(bufn, oc8, kr, f0);
            storeB<132>(bufn, oc8, kr + 64, f1);
            if (s + 2 < 8) {
                ld8(Kbase + (size_t)(2 * s + 4) * R64, true, f0);
                ld8(Kbase + (size_t)(2 * s + 5) * R64, true, f1);
            }
        }
        float acc[2][4] = {{0.f, 0.f, 0.f, 0.f}, {0.f, 0.f, 0.f, 0.f}};
#pragma unroll
        for (int o = 0; o < 8; o++) {
#pragma unroll
            for (int nt = 0; nt < 2; nt++)
                mma_p(acc[nt], aF[o], loadB<132>(bufc, o, tig, nt * 64 + nBf + gid));
        }
#pragma unroll
        for (int nt = 0; nt < 2; nt++) {
            int col = s * 128 + nt * 64 + nBf + 2 * tig;
            *(float2*)&Sb[(mB + gid) * SB_STR + col] = make_float2(acc[nt][0], acc[nt][1]);
            *(float2*)&Sb[(mB + gid + 8) * SB_STR + col] = make_float2(acc[nt][2], acc[nt][3]);
        }
        __syncthreads();
    }

    // ================= phase 2: bd band, 9 strips x 128 =================
    const int lStart = (Tc - 1) - (q0 + 31);
#pragma unroll
    for (int o = 0; o < 8; o++) aF[o] = loadA<2>(Av, o, rbw, gid, tig);
#define LDP(dst, l)                                                        \
    do {                                                                   \
        int _l = (l);                                                      \
        if (_l < Lc) ld8(P + (size_t)_l * Dc + h * HSc + oc8 * 8, true, dst); \
        else { _Pragma("unroll") for (int _i = 0; _i < 8; _i++) (dst)[_i] = 0.f; } \
    } while (0)
    LDP(f0, lStart + kr);
    LDP(f1, lStart + kr + 64);
    storeB<132>(Bf, oc8, kr, f0);
    storeB<132>(Bf, oc8, kr + 64, f1);
    __syncthreads();
    LDP(f0, lStart + 128 + kr);
    LDP(f1, lStart + 128 + kr + 64);
    for (int s = 0; s < 9; s++) {
        int lBase = lStart + s * 128;
        const uint32_t* bufc = Bf + (s & 1) * BF_STR;
        if (s + 1 < 9) {
            uint32_t* bufn = Bf + ((s + 1) & 1) * BF_STR;
            storeB<132>(bufn, oc8, kr, f0);
            storeB<132>(bufn, oc8, kr + 64, f1);
            if (s + 2 < 9) {
                LDP(f0, lStart + (s + 2) * 128 + kr);
                LDP(f1, lStart + (s + 2) * 128 + kr + 64);
            }
        }
        float acc[2][4] = {{0.f, 0.f, 0.f, 0.f}, {0.f, 0.f, 0.f, 0.f}};
#pragma unroll
        for (int o = 0; o < 8; o++) {
#pragma unroll
            for (int nt = 0; nt < 2; nt++)
                mma_p(acc[nt], aF[o], loadB<132>(bufc, o, tig, nt * 64 + nBf + gid));
        }
#pragma unroll
        for (int nt = 0; nt < 2; nt++) {
            int lc = lBase + nt * 64 + nBf + 2 * tig;
            int m = mB + gid;
            int j = (q0 + m) + lc - (Tc - 1);
            if (j >= 0 && j < Tc) Sb[m * SB_STR + j] += acc[nt][0];
            if (j + 1 >= 0 && j + 1 < Tc) Sb[m * SB_STR + j + 1] += acc[nt][1];
            int j2 = j + 8;
            if (j2 >= 0 && j2 < Tc) Sb[(m + 8) * SB_STR + j2] += acc[nt][2];
            if (j2 + 1 >= 0 && j2 + 1 < Tc) Sb[(m + 8) * SB_STR + j2 + 1] += acc[nt][3];
        }
        __syncthreads();
    }

    // ===== phase 3a: row max (2 rows/warp) =====
#pragma unroll
    for (int rr = 0; rr < 2; rr++) {
        int row_i = w * 2 + rr;
        const float* row = Sb + row_i * SB_STR;
        float mx = -3.4e38f;
        for (int c = lane; c < Tc; c += 32) mx = fmaxf(mx, row[c]);
#pragma unroll
        for (int o = 16; o; o >>= 1) mx = fmaxf(mx, __shfl_xor_sync(0xffffffffu, mx, o));
        if (lane == 0) mx_s[row_i] = mx;
    }
    __syncthreads();

    // ===== phase 4: exp (FMA) + ctx, 8 strips x 128 V rows =====
    const int row_e = t >> 4;
    const int ce = (t & 15) * 4;
    const float mxc = mx_s[row_e] * EXP_SCALE;
    float psum = 0.f;
    float* erow = Sb + row_e * SB_STR;

#define EXPCHUNK(base)                                                      \
    do {                                                                    \
        float4 x0 = *(float4*)&erow[(base)];                                \
        x0.x = fexp2(fmaf(x0.x, EXP_SCALE, -mxc));                          \
        x0.y = fexp2(fmaf(x0.y, EXP_SCALE, -mxc));                          \
        x0.z = fexp2(fmaf(x0.z, EXP_SCALE, -mxc));                          \
        x0.w = fexp2(fmaf(x0.w, EXP_SCALE, -mxc));                          \
        *(float4*)&erow[(base)] = x0;                                       \
        psum += x0.x + x0.y + x0.z + x0.w;                                  \
    } while (0)

    EXPCHUNK(ce);
    EXPCHUNK(64 + ce);

    float acc2[4] = {0.f, 0.f, 0.f, 0.f};
    const float* Vbase = V + ((size_t)(zb * Tc) + kr) * Dc + h * HSc + oc8 * 8;
#define STV(buf, rowi, f)                                                     \
    do {                                                                      \
        uint32_t* dst = (buf) + (rowi) * 72 + oc8 * 8;                        \
        *(uint4*)(dst + 0) = make_uint4(tf32_of((f)[0]), tf32_of((f)[1]),     \
                                        tf32_of((f)[2]), tf32_of((f)[3]));    \
        *(uint4*)(dst + 4) = make_uint4(tf32_of((f)[4]), tf32_of((f)[5]),     \
                                        tf32_of((f)[6]), tf32_of((f)[7]));    \
    } while (0)

    ld8(Vbase, true, f0);
    ld8(Vbase + R64, true, f1);
    STV(Bf, kr, f0);
    STV(Bf, kr + 64, f1);
    __syncthreads();
    ld8(Vbase + 2 * R64, true, f0);
    ld8(Vbase + 3 * R64, true, f1);
    for (int s = 0; s < 8; s++) {
        const uint32_t* Vtc = Bf + (s & 1) * BF_STR;
        if (s + 1 < 8) {
            uint32_t* Vtn = Bf + ((s + 1) & 1) * BF_STR;
            STV(Vtn, kr, f0);
            STV(Vtn, kr + 64, f1);
            if (s + 2 < 8) {
                ld8(Vbase + (size_t)(2 * s + 4) * R64, true, f0);
                ld8(Vbase + (size_t)(2 * s + 5) * R64, true, f1);
            }
            EXPCHUNK((s + 1) * 128 + ce);
            EXPCHUNK((s + 1) * 128 + 64 + ce);
        }

        const float* ar0 = Sb + (mB + gid) * SB_STR + s * 128;
        const float* ar8 = ar0 + 8 * SB_STR;
#pragma unroll
        for (int o = 0; o < 16; o++) {
            uint4 a;
            a.x = tf32_of(ar0[o * 8 + tig]);
            a.y = tf32_of(ar8[o * 8 + tig]);
            a.z = tf32_of(ar0[o * 8 + tig + 4]);
            a.w = tf32_of(ar8[o * 8 + tig + 4]);
            int c = nBf + gid;
            uint2 b;
            b.x = Vtc[(o * 8 + tig) * 72 + c];
            b.y = Vtc[(o * 8 + tig + 4) * 72 + c];
            mma_p(acc2, a, b);
        }
        __syncthreads();
    }

    // ---- row-sum reduce over 16 lanes sharing a row ----
#pragma unroll
    for (int o = 8; o; o >>= 1) psum += __shfl_xor_sync(0xffffffffu, psum, o);
    if ((lane & 15) == 0) inv_s[row_e] = 1.f / psum;
    __syncthreads();

    // ---- write probs = e * inv ----
    {
        float* pb = probs + ((size_t)bh << 20) + (size_t)q0 * Tc;
#pragma unroll 4
        for (int it = 0; it < 16; it++) {
            int idx = it * 512 + t;
            int r = idx >> 8, c4 = (idx & 255) * 4;
            float iv = inv_s[r];
            float4 val = *(float4*)&Sb[r * SB_STR + c4];
            val.x *= iv; val.y *= iv; val.z *= iv; val.w *= iv;
            *(float4*)(pb + (size_t)r * Tc + c4) = val;
        }
    }

    // ---- ctx epilogue: scale by inv ----
    {
        int r = q0 + mB + gid;
        float iv0 = inv_s[mB + gid], iv8 = inv_s[mB + gid + 8];
        int c = nBf + 2 * tig;
        *(float2*)(ctx + ((size_t)(zb * Tc) + r) * Dc + h * HSc + c) =
            make_float2(acc2[0] * iv0, acc2[1] * iv0);
        *(float2*)(ctx + ((size_t)(zb * Tc) + r + 8) * Dc + h * HSc + c) =
            make_float2(acc2[2] * iv8, acc2[3] * iv8);
    }
}

// ============================================================
extern "C" void kernel_launch(void* const* d_in, const int* in_sizes, int n_in,
                              void* d_out, int out_size) {
    const float* hs  = (const float*)d_in[0];
    const float* rpe = (const float*)d_in[1];
    const float* Wq  = (const float*)d_in[2];
    const float* bq  = (const float*)d_in[3];
    const float* Wk  = (const float*)d_in[4];
    const float* bk  = (const float*)d_in[5];
    const float* Wv  = (const float*)d_in[6];
    const float* bv  = (const float*)d_in[7];
    const float* Wo  = (const float*)d_in[8];
    const float* bo  = (const float*)d_in[9];
    const float* Wp  = (const float*)d_in[10];
    const float* pu  = (const float*)d_in[11];
    const float* pvb = (const float*)d_in[12];

    float* out = (float*)d_out;
    float* S   = out + (size_t)Bc * Tc * Dc;

    float *pq, *pk, *pv, *pp, *pctx;
    cudaGetSymbolAddress((void**)&pq,   g_q);
    cudaGetSymbolAddress((void**)&pk,   g_k);
    cudaGetSymbolAddress((void**)&pv,   g_v);
    cudaGetSymbolAddress((void**)&pp,   g_p);
    cudaGetSymbolAddress((void**)&pctx, g_ctx);

    cudaFuncSetAttribute(fused_attn, cudaFuncAttributeMaxDynamicSharedMemorySize,
                         FUSED_SMEM_BYTES);

    gemm_qkvp<<<dim3(32, 32), 256>>>(hs, rpe, Wq, Wk, Wv, Wp, bq, bk, bv,
                                     pq, pk, pv, pp);

    fused_attn<<<dim3(Tc / 32, Bc * Hc), 512, FUSED_SMEM_BYTES>>>(
        pq, pk, pp, pv, pu, pvb, S, pctx);

    gemm_tc_nt<<<dim3(8, 32), 256>>>(pctx, Wo, bo, out, Bc * Tc, Dc, Dc);
}

// round 16
// speedup vs baseline: 1.2149x; 1.0685x over previous
#include <cuda_runtime.h>
#include <math.h>
#include <stdint.h>

#define Bc 4
#define Tc 1024
#define Dc 1024
#define Hc 16
#define HSc 64
#define Lc 2047

__device__ float g_q[Bc * Tc * Dc];
__device__ float g_k[Bc * Tc * Dc];
__device__ float g_v[Bc * Tc * Dc];
__device__ float g_p[Lc * Dc];
__device__ float g_ctx[Bc * Tc * Dc];
// pre-rounded (tf32) copies of inputs
__device__ float g_hsr[Bc * Tc * Dc];
__device__ float g_rper[Lc * Dc];
__device__ float g_wq[Dc * Dc];
__device__ float g_wk[Dc * Dc];
__device__ float g_wv[Dc * Dc];
__device__ float g_wp[Dc * Dc];
__device__ float g_wo[Dc * Dc];

__device__ __forceinline__ uint32_t tf32_of(float x) {
    uint32_t r;
    asm("cvt.rna.tf32.f32 %0, %1;" : "=r"(r) : "f"(x));
    return r;
}
__device__ __forceinline__ float tf32f(float x) { return __uint_as_float(tf32_of(x)); }
__device__ __forceinline__ void mma_p(float* d, uint4 a, uint2 b) {
    asm volatile(
        "mma.sync.aligned.m16n8k8.row.col.f32.tf32.tf32.f32 "
        "{%0,%1,%2,%3},{%4,%5,%6,%7},{%8,%9},{%0,%1,%2,%3};"
        : "+f"(d[0]), "+f"(d[1]), "+f"(d[2]), "+f"(d[3])
        : "r"(a.x), "r"(a.y), "r"(a.z), "r"(a.w), "r"(b.x), "r"(b.y));
}

// FMA-pipe exp: 2^y via magic-round + degree-5 poly.
__device__ __forceinline__ float fexp2(float y) {
    y = fmaxf(y, -100.f);
    float rn = y + 12582912.f;
    int n = __float_as_int(rn) - 0x4B400000;
    float f = y - (rn - 12582912.f);
    float p = 1.3333558e-3f;
    p = fmaf(p, f, 9.6181290e-3f);
    p = fmaf(p, f, 5.5504108e-2f);
    p = fmaf(p, f, 2.4022650e-1f);
    p = fmaf(p, f, 6.9314718e-1f);
    p = fmaf(p, f, 1.0f);
    return __int_as_float(__float_as_int(p) + (n << 23));
}
#define EXP_SCALE 0.18033688011112042f   /* 0.125 * log2(e) */

// ---- packed A fragments (cvt at store; for q+u/q+v sums) ----
template <int RB>
__device__ __forceinline__ void storeA(uint32_t* sA, int oct, int r, const float* f) {
    uint32_t* b = sA + oct * (RB * 128 + 8) + (r >> 4) * 128 + (r & 7) * 16 + ((r >> 3) & 1);
    int gs = r & 3;
#pragma unroll
    for (int p = 0; p < 4; p++) {
        int tq = p ^ gs;
        b[p * 4] = tf32_of(f[tq]);
        b[p * 4 + 2] = tf32_of(f[tq + 4]);
    }
}
// raw-bit variant (inputs already tf32-rounded)
template <int RB>
__device__ __forceinline__ void storeA_raw(uint32_t* sA, int oct, int r, const float* f) {
    uint32_t* b = sA + oct * (RB * 128 + 8) + (r >> 4) * 128 + (r & 7) * 16 + ((r >> 3) & 1);
    int gs = r & 3;
#pragma unroll
    for (int p = 0; p < 4; p++) {
        int tq = p ^ gs;
        b[p * 4] = __float_as_uint(f[tq]);
        b[p * 4 + 2] = __float_as_uint(f[tq + 4]);
    }
}
template <int RB>
__device__ __forceinline__ uint4 loadA(const uint32_t* sA, int oct, int rb, int gid, int tig) {
    return *(const uint4*)(sA + oct * (RB * 128 + 8) + rb * 128 + gid * 16 +
                           ((tig ^ (gid & 3)) << 2));
}
// ---- packed B fragments: raw-bit staging (inputs pre-rounded) ----
template <int S>
__device__ __forceinline__ void storeB_raw(uint32_t* sB, int oct, int c, const float* f) {
    uint32_t* b = sB + oct * (S * 8 + 8) + c * 2;
#pragma unroll
    for (int tq = 0; tq < 4; tq++)
        *(uint2*)(b + tq * S * 2) =
            make_uint2(__float_as_uint(f[tq]), __float_as_uint(f[tq + 4]));
}
template <int S>
__device__ __forceinline__ uint2 loadB(const uint32_t* sB, int oct, int tig, int c) {
    return *(const uint2*)(sB + oct * (S * 8 + 8) + (tig * S + c) * 2);
}

__device__ __forceinline__ void ld8(const float* p, bool ok, float* f) {
    float4 z = make_float4(0.f, 0.f, 0.f, 0.f);
    float4 x0 = ok ? *(const float4*)p : z;
    float4 x1 = ok ? *(const float4*)(p + 4) : z;
    f[0] = x0.x; f[1] = x0.y; f[2] = x0.z; f[3] = x0.w;
    f[4] = x1.x; f[5] = x1.y; f[6] = x1.z; f[7] = x1.w;
}

// ============================================================
// prep: round 7 tensors to tf32 once
// ============================================================
struct RArgs {
    const float* src[7];
    float* dst[7];
    int n4[7];
};
__global__ void round_all(RArgs a) {
    for (int s = 0; s < 7; s++) {
        const float4* src = (const float4*)a.src[s];
        float4* dst = (float4*)a.dst[s];
        int n4 = a.n4[s];
        for (int i = blockIdx.x * blockDim.x + threadIdx.x; i < n4;
             i += gridDim.x * blockDim.x) {
            float4 v = src[i];
            v.x = tf32f(v.x); v.y = tf32f(v.y);
            v.z = tf32f(v.z); v.w = tf32f(v.w);
            dst[i] = v;
        }
    }
}

// ============================================================
// GEMM body: inputs pre-rounded tf32; no CVT in staging.
// RND: round outputs to tf32 (for q/k/v/p feeding the fused kernel).
// ============================================================
template <bool RND>
__device__ __forceinline__ void gemm_body(const float* __restrict__ A,
                                          const float* __restrict__ W,
                                          const float* __restrict__ bias,
                                          float* __restrict__ C,
                                          int M, int N, int K, int m0, int n0) {
    __shared__ __align__(16) uint32_t sA[2][2 * (8 * 128 + 8)];
    __shared__ __align__(16) uint32_t sB[2][2 * (132 * 8 + 8)];
    const int tid = threadIdx.x;
    const int lrow = tid >> 1, oct = tid & 1, lk = oct * 8;
    const int lane = tid & 31, wid = tid >> 5;
    const int rb0 = (wid >> 1) * 2, nB = (wid & 1) * 64;
    const int gid = lane >> 2, tig = lane & 3;

    float acc[2][8][4];
#pragma unroll
    for (int i = 0; i < 2; i++)
#pragma unroll
        for (int j = 0; j < 8; j++)
#pragma unroll
            for (int c = 0; c < 4; c++) acc[i][j][c] = 0.f;

    const bool av = (m0 + lrow) < M, wv = (n0 + lrow) < N;
    const float* Ar = A + (size_t)(m0 + lrow) * K + lk;
    const float* Wr = W + (size_t)(n0 + lrow) * K + lk;
    float fA[8], fB[8];
    ld8(Ar, av, fA);
    ld8(Wr, wv, fB);
    storeA_raw<8>(sA[0], oct, lrow, fA);
    storeB_raw<132>(sB[0], oct, lrow, fB);
    __syncthreads();

    const int nk = K / 16;
    for (int kt = 0; kt < nk; kt++) {
        const int cur = kt & 1;
        const bool more = (kt + 1) < nk;
        if (more) {
            ld8(Ar + (kt + 1) * 16, av, fA);
            ld8(Wr + (kt + 1) * 16, wv, fB);
        }
#pragma unroll
        for (int o = 0; o < 2; o++) {
            uint4 a0 = loadA<8>(sA[cur], o, rb0, gid, tig);
            uint4 a1 = loadA<8>(sA[cur], o, rb0 + 1, gid, tig);
#pragma unroll
            for (int nt = 0; nt < 8; nt++) {
                uint2 bv = loadB<132>(sB[cur], o, tig, nB + nt * 8 + gid);
                mma_p(acc[0][nt], a0, bv);
                mma_p(acc[1][nt], a1, bv);
            }
        }
        if (more) {
            storeA_raw<8>(sA[cur ^ 1], oct, lrow, fA);
            storeB_raw<132>(sB[cur ^ 1], oct, lrow, fB);
            __syncthreads();
        }
    }

#pragma unroll
    for (int mt = 0; mt < 2; mt++) {
        int r = m0 + (rb0 + mt) * 16 + gid;
#pragma unroll
        for (int nt = 0; nt < 8; nt++) {
            int c = n0 + nB + nt * 8 + 2 * tig;
            float b0v = bias ? bias[c] : 0.f;
            float b1v = bias ? bias[c + 1] : 0.f;
            float v00 = acc[mt][nt][0] + b0v, v01 = acc[mt][nt][1] + b1v;
            float v10 = acc[mt][nt][2] + b0v, v11 = acc[mt][nt][3] + b1v;
            if (RND) {
                v00 = tf32f(v00); v01 = tf32f(v01);
                v10 = tf32f(v10); v11 = tf32f(v11);
            }
            if (r < M)
                *(float2*)(C + (size_t)r * N + c) = make_float2(v00, v01);
            if (r + 8 < M)
                *(float2*)(C + (size_t)(r + 8) * N + c) = make_float2(v10, v11);
        }
    }
}

__global__ __launch_bounds__(256, 2) void gemm_out(
    const float* __restrict__ A, const float* __restrict__ W,
    const float* __restrict__ bias, float* __restrict__ C, int M, int N, int K) {
    gemm_body<false>(A, W, bias, C, M, N, K, blockIdx.y * 128, blockIdx.x * 128);
}

// QKV + pos projections (outputs rounded to tf32). grid (32, 32).
__global__ __launch_bounds__(256, 2) void gemm_qkvp(
    const float* __restrict__ A, const float* __restrict__ rpe,
    const float* __restrict__ Wq, const float* __restrict__ Wk, const float* __restrict__ Wv,
    const float* __restrict__ Wp,
    const float* __restrict__ bq, const float* __restrict__ bk, const float* __restrict__ bv,
    float* __restrict__ Cq, float* __restrict__ Ck, float* __restrict__ Cv,
    float* __restrict__ Cp) {
    const int sel = blockIdx.x >> 3;
    if (sel == 3) {
        if (blockIdx.y >= 16) return;
        gemm_body<true>(rpe, Wp, nullptr, Cp, Lc, Dc, Dc,
                        blockIdx.y * 128, (blockIdx.x & 7) * 128);
        return;
    }
    const float* W = (sel == 0) ? Wq : (sel == 1) ? Wk : Wv;
    const float* bias = (sel == 0) ? bq : (sel == 1) ? bk : bv;
    float* C = (sel == 0) ? Cq : (sel == 1) ? Ck : Cv;
    gemm_body<true>(A, W, bias, C, Bc * Tc, Dc, Dc,
                    blockIdx.y * 128, (blockIdx.x & 7) * 128);
}

// ============================================================
// FUSED attention per (bh, 32-row q tile) — R13 structure (proven),
// raw-bit staging for pre-rounded K/P/V; FMA exp; 512 threads.
// smem (u32): Sb 32*1028 | Au 8*264 | Av 8*264 | Bf 2*4608 | mx 32 | inv 32
// ============================================================
#define SB_STR 1028
#define AU_OFF (32 * SB_STR)
#define AV_OFF (AU_OFF + 8 * 264)
#define BF_OFF (AV_OFF + 8 * 264)
#define BF_STR 4608
#define MX_OFF (BF_OFF + 2 * BF_STR)
#define INV_OFF (MX_OFF + 32)
#define FUSED_SMEM_BYTES ((INV_OFF + 32) * 4)

__global__ __launch_bounds__(512, 1) void fused_attn(
    const float* __restrict__ Q, const float* __restrict__ K,
    const float* __restrict__ P, const float* __restrict__ V,
    const float* __restrict__ u, const float* __restrict__ vb,
    float* __restrict__ probs, float* __restrict__ ctx) {
    extern __shared__ __align__(16) uint32_t su[];
    float* Sb = (float*)su;
    uint32_t* Au = su + AU_OFF;
    uint32_t* Av = su + AV_OFF;
    uint32_t* Bf = su + BF_OFF;
    float* mx_s = (float*)(su + MX_OFF);
    float* inv_s = (float*)(su + INV_OFF);

    const int t = threadIdx.x;
    const int bh = blockIdx.y, zb = bh >> 4, h = bh & 15;
    const int q0 = blockIdx.x * 32;
    const int lane = t & 31, w = t >> 5;
    const int mB = (w & 1) * 16, rbw = w & 1, nBf = (w >> 1) * 8;
    const int gid = lane >> 2, tig = lane & 3;

    // ---- stage q+u (t<256) / q+v (t>=256) as packed A fragments ----
    {
        int tt = t & 255;
        int qr = tt >> 3, o = tt & 7;
        const float* qp = Q + ((size_t)(zb * Tc) + q0 + qr) * Dc + h * HSc + o * 8;
        float a[8], bb[8];
        ld8(qp, true, a);
        if (t < 256) {
            ld8(u + h * HSc + o * 8, true, bb);
#pragma unroll
            for (int i = 0; i < 8; i++) bb[i] += a[i];
            storeA<2>(Au, o, qr, bb);
        } else {
            ld8(vb + h * HSc + o * 8, true, bb);
#pragma unroll
            for (int i = 0; i < 8; i++) bb[i] += a[i];
            storeA<2>(Av, o, qr, bb);
        }
    }

    const int kr = t >> 3, oc8 = t & 7;   // staging: 64 rows x 8 octs
    float f0[8];
    uint4 aF[8];

    // ================= phase 1: ac = (q+u) K^T =================
    {
        const float* kp = K + ((size_t)(zb * Tc) + kr) * Dc + h * HSc + oc8 * 8;
        ld8(kp, true, f0);
        storeB_raw<68>(Bf, oc8, kr, f0);
    }
    __syncthreads();
#pragma unroll
    for (int o = 0; o < 8; o++) aF[o] = loadA<2>(Au, o, rbw, gid, tig);
    {
        const float* kp = K + ((size_t)(zb * Tc) + 64 + kr) * Dc + h * HSc + oc8 * 8;
        ld8(kp, true, f0);
    }
    for (int s = 0; s < 16; s++) {
        const uint32_t* bufc = Bf + (s & 1) * BF_STR;
        if (s + 1 < 16) {
            uint32_t* bufn = Bf + ((s + 1) & 1) * BF_STR;
            storeB_raw<68>(bufn, oc8, kr, f0);
            if (s + 2 < 16) {
                const float* kp =
                    K + ((size_t)(zb * Tc) + (s + 2) * 64 + kr) * Dc + h * HSc + oc8 * 8;
                ld8(kp, true, f0);
            }
        }
        float acc[4] = {0.f, 0.f, 0.f, 0.f};
#pragma unroll
        for (int o = 0; o < 8; o++)
            mma_p(acc, aF[o], loadB<68>(bufc, o, tig, nBf + gid));
        int col = s * 64 + nBf + 2 * tig;
        *(float2*)&Sb[(mB + gid) * SB_STR + col] = make_float2(acc[0], acc[1]);
        *(float2*)&Sb[(mB + gid + 8) * SB_STR + col] = make_float2(acc[2], acc[3]);
        __syncthreads();
    }

    // ================= phase 2: bd band, scatter-add =================
    const int lStart = (Tc - 1) - (q0 + 31);
#pragma unroll
    for (int o = 0; o < 8; o++) aF[o] = loadA<2>(Av, o, rbw, gid, tig);
    {
        int l = lStart + kr;
        if (l < Lc) ld8(P + (size_t)l * Dc + h * HSc + oc8 * 8, true, f0);
        else {
#pragma unroll
            for (int i = 0; i < 8; i++) f0[i] = 0.f;
        }
        storeB_raw<68>(Bf, oc8, kr, f0);
    }
    __syncthreads();
    {
        int l = lStart + 64 + kr;
        if (l < Lc) ld8(P + (size_t)l * Dc + h * HSc + oc8 * 8, true, f0);
        else {
#pragma unroll
            for (int i = 0; i < 8; i++) f0[i] = 0.f;
        }
    }
    for (int s = 0; s < 17; s++) {
        int lBase = lStart + s * 64;
        const uint32_t* bufc = Bf + (s & 1) * BF_STR;
        if (s + 1 < 17) {
            uint32_t* bufn = Bf + ((s + 1) & 1) * BF_STR;
            storeB_raw<68>(bufn, oc8, kr, f0);
            if (s + 2 < 17) {
                int l = lStart + (s + 2) * 64 + kr;
                if (l < Lc) ld8(P + (size_t)l * Dc + h * HSc + oc8 * 8, true, f0);
                else {
#pragma unroll
                    for (int i = 0; i < 8; i++) f0[i] = 0.f;
                }
            }
        }
        float acc[4] = {0.f, 0.f, 0.f, 0.f};
#pragma unroll
        for (int o = 0; o < 8; o++)
            mma_p(acc, aF[o], loadB<68>(bufc, o, tig, nBf + gid));
        int lc = lBase + nBf + 2 * tig;
        int m = mB + gid;
        int j = (q0 + m) + lc - (Tc - 1);
        if (j >= 0 && j < Tc) Sb[m * SB_STR + j] += acc[0];
        if (j + 1 >= 0 && j + 1 < Tc) Sb[m * SB_STR + j + 1] += acc[1];
        int j2 = j + 8;
        if (j2 >= 0 && j2 < Tc) Sb[(m + 8) * SB_STR + j2] += acc[2];
        if (j2 + 1 >= 0 && j2 + 1 < Tc) Sb[(m + 8) * SB_STR + j2 + 1] += acc[3];
        __syncthreads();
    }

    // ===== phase 3a: row max (2 rows/warp) =====
#pragma unroll
    for (int rr = 0; rr < 2; rr++) {
        int row_i = w * 2 + rr;
        const float* row = Sb + row_i * SB_STR;
        float mx = -3.4e38f;
        for (int c = lane; c < Tc; c += 32) mx = fmaxf(mx, row[c]);
#pragma unroll
        for (int o = 16; o; o >>= 1) mx = fmaxf(mx, __shfl_xor_sync(0xffffffffu, mx, o));
        if (lane == 0) mx_s[row_i] = mx;
    }
    __syncthreads();

    // ===== phase 4: exp (FMA) + ctx, double-buffered V =====
    const int row_e = t >> 4;
    const int ce = (t & 15) * 4;
    const float mxc = mx_s[row_e] * EXP_SCALE;
    float psum = 0.f;
    float* erow = Sb + row_e * SB_STR;

    {   // exp strip 0
        float4 x0 = *(float4*)&erow[ce];
        x0.x = fexp2(fmaf(x0.x, EXP_SCALE, -mxc)); x0.y = fexp2(fmaf(x0.y, EXP_SCALE, -mxc));
        x0.z = fexp2(fmaf(x0.z, EXP_SCALE, -mxc)); x0.w = fexp2(fmaf(x0.w, EXP_SCALE, -mxc));
        *(float4*)&erow[ce] = x0;
        psum += x0.x + x0.y + x0.z + x0.w;
    }

    float acc2[4] = {0.f, 0.f, 0.f, 0.f};
    float fv[8];
    {
        const float* vp = V + ((size_t)(zb * Tc) + kr) * Dc + h * HSc + oc8 * 8;
        ld8(vp, true, fv);
        uint32_t* dst = Bf + kr * 72 + oc8 * 8;
        *(uint4*)(dst + 0) = make_uint4(__float_as_uint(fv[0]), __float_as_uint(fv[1]),
                                        __float_as_uint(fv[2]), __float_as_uint(fv[3]));
        *(uint4*)(dst + 4) = make_uint4(__float_as_uint(fv[4]), __float_as_uint(fv[5]),
                                        __float_as_uint(fv[6]), __float_as_uint(fv[7]));
    }
    __syncthreads();
    {
        const float* vp = V + ((size_t)(zb * Tc) + 64 + kr) * Dc + h * HSc + oc8 * 8;
        ld8(vp, true, fv);
    }
    for (int s = 0; s < 16; s++) {
        const uint32_t* Vtc = Bf + (s & 1) * BF_STR;
        if (s + 1 < 16) {
            uint32_t* Vtn = Bf + ((s + 1) & 1) * BF_STR;
            uint32_t* dst = Vtn + kr * 72 + oc8 * 8;
            *(uint4*)(dst + 0) = make_uint4(__float_as_uint(fv[0]), __float_as_uint(fv[1]),
                                            __float_as_uint(fv[2]), __float_as_uint(fv[3]));
            *(uint4*)(dst + 4) = make_uint4(__float_as_uint(fv[4]), __float_as_uint(fv[5]),
                                            __float_as_uint(fv[6]), __float_as_uint(fv[7]));
            if (s + 2 < 16) {
                const float* vp =
                    V + ((size_t)(zb * Tc) + (s + 2) * 64 + kr) * Dc + h * HSc + oc8 * 8;
                ld8(vp, true, fv);
            }
            float* ep = erow + (s + 1) * 64 + ce;
            float4 x0 = *(float4*)ep;
            x0.x = fexp2(fmaf(x0.x, EXP_SCALE, -mxc)); x0.y = fexp2(fmaf(x0.y, EXP_SCALE, -mxc));
            x0.z = fexp2(fmaf(x0.z, EXP_SCALE, -mxc)); x0.w = fexp2(fmaf(x0.w, EXP_SCALE, -mxc));
            *(float4*)ep = x0;
            psum += x0.x + x0.y + x0.z + x0.w;
        }

        const float* ar0 = Sb + (mB + gid) * SB_STR + s * 64;
        const float* ar8 = ar0 + 8 * SB_STR;
#pragma unroll
        for (int o = 0; o < 8; o++) {
            uint4 a;
            a.x = tf32_of(ar0[o * 8 + tig]);
            a.y = tf32_of(ar8[o * 8 + tig]);
            a.z = tf32_of(ar0[o * 8 + tig + 4]);
            a.w = tf32_of(ar8[o * 8 + tig + 4]);
            int c = nBf + gid;
            uint2 b;
            b.x = Vtc[(o * 8 + tig) * 72 + c];
            b.y = Vtc[(o * 8 + tig + 4) * 72 + c];
            mma_p(acc2, a, b);
        }
        __syncthreads();
    }

    // ---- row-sum reduce over 16 lanes sharing a row ----
#pragma unroll
    for (int o = 8; o; o >>= 1) psum += __shfl_xor_sync(0xffffffffu, psum, o);
    if ((lane & 15) == 0) inv_s[row_e] = 1.f / psum;
    __syncthreads();

    // ---- write probs = e * inv ----
    {
        float* pb = probs + ((size_t)bh << 20) + (size_t)q0 * Tc;
#pragma unroll 4
        for (int it = 0; it < 16; it++) {
            int idx = it * 512 + t;
            int r = idx >> 8, c4 = (idx & 255) * 4;
            float iv = inv_s[r];
            float4 val = *(float4*)&Sb[r * SB_STR + c4];
            val.x *= iv; val.y *= iv; val.z *= iv; val.w *= iv;
            *(float4*)(pb + (size_t)r * Tc + c4) = val;
        }
    }

    // ---- ctx epilogue: scale by inv, round to tf32 (out-GEMM stages raw) ----
    {
        int r = q0 + mB + gid;
        float iv0 = inv_s[mB + gid], iv8 = inv_s[mB + gid + 8];
        int c = nBf + 2 * tig;
        *(float2*)(ctx + ((size_t)(zb * Tc) + r) * Dc + h * HSc + c) =
            make_float2(tf32f(acc2[0] * iv0), tf32f(acc2[1] * iv0));
        *(float2*)(ctx + ((size_t)(zb * Tc) + r + 8) * Dc + h * HSc + c) =
            make_float2(tf32f(acc2[2] * iv8), tf32f(acc2[3] * iv8));
    }
}

// ============================================================
extern "C" void kernel_launch(void* const* d_in, const int* in_sizes, int n_in,
                              void* d_out, int out_size) {
    const float* hs  = (const float*)d_in[0];
    const float* rpe = (const float*)d_in[1];
    const float* Wq  = (const float*)d_in[2];
    const float* bq  = (const float*)d_in[3];
    const float* Wk  = (const float*)d_in[4];
    const float* bk  = (const float*)d_in[5];
    const float* Wv  = (const float*)d_in[6];
    const float* bv  = (const float*)d_in[7];
    const float* Wo  = (const float*)d_in[8];
    const float* bo  = (const float*)d_in[9];
    const float* Wp  = (const float*)d_in[10];
    const float* pu  = (const float*)d_in[11];
    const float* pvb = (const float*)d_in[12];

    float* out = (float*)d_out;
    float* S   = out + (size_t)Bc * Tc * Dc;

    float *pq, *pk, *pv, *pp, *pctx;
    float *hsr, *rper, *wq, *wk, *wv, *wp, *wo;
    cudaGetSymbolAddress((void**)&pq,   g_q);
    cudaGetSymbolAddress((void**)&pk,   g_k);
    cudaGetSymbolAddress((void**)&pv,   g_v);
    cudaGetSymbolAddress((void**)&pp,   g_p);
    cudaGetSymbolAddress((void**)&pctx, g_ctx);
    cudaGetSymbolAddress((void**)&hsr,  g_hsr);
    cudaGetSymbolAddress((void**)&rper, g_rper);
    cudaGetSymbolAddress((void**)&wq,   g_wq);
    cudaGetSymbolAddress((void**)&wk,   g_wk);
    cudaGetSymbolAddress((void**)&wv,   g_wv);
    cudaGetSymbolAddress((void**)&wp,   g_wp);
    cudaGetSymbolAddress((void**)&wo,   g_wo);

    cudaFuncSetAttribute(fused_attn, cudaFuncAttributeMaxDynamicSharedMemorySize,
                         FUSED_SMEM_BYTES);

    RArgs ra;
    ra.src[0] = hs;  ra.dst[0] = hsr;  ra.n4[0] = (Bc * Tc * Dc) / 4;
    ra.src[1] = rpe; ra.dst[1] = rper; ra.n4[1] = (Lc * Dc) / 4;
    ra.src[2] = Wq;  ra.dst[2] = wq;   ra.n4[2] = (Dc * Dc) / 4;
    ra.src[3] = Wk;  ra.dst[3] = wk;   ra.n4[3] = (Dc * Dc) / 4;
    ra.src[4] = Wv;  ra.dst[4] = wv;   ra.n4[4] = (Dc * Dc) / 4;
    ra.src[5] = Wp;  ra.dst[5] = wp;   ra.n4[5] = (Dc * Dc) / 4;
    ra.src[6] = Wo;  ra.dst[6] = wo;   ra.n4[6] = (Dc * Dc) / 4;
    round_all<<<1024, 256>>>(ra);

    gemm_qkvp<<<dim3(32, 32), 256>>>(hsr, rper, wq, wk, wv, wp, bq, bk, bv,
                                     pq, pk, pv, pp);

    fused_attn<<<dim3(Tc / 32, Bc * Hc), 512, FUSED_SMEM_BYTES>>>(
        pq, pk, pp, pv, pu, pvb, S, pctx);

    gemm_out<<<dim3(8, 32), 256>>>(pctx, wo, bo, out, Bc * Tc, Dc, Dc);
}

// round 17
// speedup vs baseline: 1.2723x; 1.0473x over previous
#include <cuda_runtime.h>
#include <math.h>
#include <stdint.h>

#define Bc 4
#define Tc 1024
#define Dc 1024
#define Hc 16
#define HSc 64
#define Lc 2047

__device__ float g_q[Bc * Tc * Dc];
__device__ float g_k[Bc * Tc * Dc];
__device__ float g_v[Bc * Tc * Dc];
__device__ float g_p[Lc * Dc];
__device__ float g_ctx[Bc * Tc * Dc];
__device__ float g_hsr[Bc * Tc * Dc];
__device__ float g_rper[Lc * Dc];
__device__ float g_wq[Dc * Dc];
__device__ float g_wk[Dc * Dc];
__device__ float g_wv[Dc * Dc];
__device__ float g_wp[Dc * Dc];
__device__ float g_wo[Dc * Dc];

__device__ __forceinline__ uint32_t tf32_of(float x) {
    uint32_t r;
    asm("cvt.rna.tf32.f32 %0, %1;" : "=r"(r) : "f"(x));
    return r;
}
__device__ __forceinline__ float tf32f(float x) { return __uint_as_float(tf32_of(x)); }
__device__ __forceinline__ void mma_p(float* d, uint4 a, uint2 b) {
    asm volatile(
        "mma.sync.aligned.m16n8k8.row.col.f32.tf32.tf32.f32 "
        "{%0,%1,%2,%3},{%4,%5,%6,%7},{%8,%9},{%0,%1,%2,%3};"
        : "+f"(d[0]), "+f"(d[1]), "+f"(d[2]), "+f"(d[3])
        : "r"(a.x), "r"(a.y), "r"(a.z), "r"(a.w), "r"(b.x), "r"(b.y));
}

__device__ __forceinline__ float fexp2(float y) {
    y = fmaxf(y, -100.f);
    float rn = y + 12582912.f;
    int n = __float_as_int(rn) - 0x4B400000;
    float f = y - (rn - 12582912.f);
    float p = 1.3333558e-3f;
    p = fmaf(p, f, 9.6181290e-3f);
    p = fmaf(p, f, 5.5504108e-2f);
    p = fmaf(p, f, 2.4022650e-1f);
    p = fmaf(p, f, 6.9314718e-1f);
    p = fmaf(p, f, 1.0f);
    return __int_as_float(__float_as_int(p) + (n << 23));
}
#define EXP_SCALE 0.18033688011112042f

// cp.async helpers
__device__ __forceinline__ void cpa16(uint32_t dst, const float* src, int sz) {
    asm volatile("cp.async.ca.shared.global [%0], [%1], 16, %2;"
                 :: "r"(dst), "l"(src), "r"(sz));
}
#define CP_COMMIT() asm volatile("cp.async.commit_group;")
#define CP_WAIT2()  asm volatile("cp.async.wait_group 2;")

// ---- packed A fragments ----
template <int RB>
__device__ __forceinline__ void storeA(uint32_t* sA, int oct, int r, const float* f) {
    uint32_t* b = sA + oct * (RB * 128 + 8) + (r >> 4) * 128 + (r & 7) * 16 + ((r >> 3) & 1);
    int gs = r & 3;
#pragma unroll
    for (int p = 0; p < 4; p++) {
        int tq = p ^ gs;
        b[p * 4] = tf32_of(f[tq]);
        b[p * 4 + 2] = tf32_of(f[tq + 4]);
    }
}
template <int RB>
__device__ __forceinline__ void storeA_raw(uint32_t* sA, int oct, int r, const float* f) {
    uint32_t* b = sA + oct * (RB * 128 + 8) + (r >> 4) * 128 + (r & 7) * 16 + ((r >> 3) & 1);
    int gs = r & 3;
#pragma unroll
    for (int p = 0; p < 4; p++) {
        int tq = p ^ gs;
        b[p * 4] = __float_as_uint(f[tq]);
        b[p * 4 + 2] = __float_as_uint(f[tq + 4]);
    }
}
template <int RB>
__device__ __forceinline__ uint4 loadA(const uint32_t* sA, int oct, int rb, int gid, int tig) {
    return *(const uint4*)(sA + oct * (RB * 128 + 8) + rb * 128 + gid * 16 +
                           ((tig ^ (gid & 3)) << 2));
}
template <int S>
__device__ __forceinline__ void storeB_raw(uint32_t* sB, int oct, int c, const float* f) {
    uint32_t* b = sB + oct * (S * 8 + 8) + c * 2;
#pragma unroll
    for (int tq = 0; tq < 4; tq++)
        *(uint2*)(b + tq * S * 2) =
            make_uint2(__float_as_uint(f[tq]), __float_as_uint(f[tq + 4]));
}
template <int S>
__device__ __forceinline__ uint2 loadB(const uint32_t* sB, int oct, int tig, int c) {
    return *(const uint2*)(sB + oct * (S * 8 + 8) + (tig * S + c) * 2);
}

__device__ __forceinline__ void ld8(const float* p, bool ok, float* f) {
    float4 z = make_float4(0.f, 0.f, 0.f, 0.f);
    float4 x0 = ok ? *(const float4*)p : z;
    float4 x1 = ok ? *(const float4*)(p + 4) : z;
    f[0] = x0.x; f[1] = x0.y; f[2] = x0.z; f[3] = x0.w;
    f[4] = x1.x; f[5] = x1.y; f[6] = x1.z; f[7] = x1.w;
}

// ============================================================
// prep: round 7 tensors to tf32 once
// ============================================================
struct RArgs {
    const float* src[7];
    float* dst[7];
    int n4[7];
};
__global__ void round_all(RArgs a) {
    for (int s = 0; s < 7; s++) {
        const float4* src = (const float4*)a.src[s];
        float4* dst = (float4*)a.dst[s];
        int n4 = a.n4[s];
        for (int i = blockIdx.x * blockDim.x + threadIdx.x; i < n4;
             i += gridDim.x * blockDim.x) {
            float4 v = src[i];
            v.x = tf32f(v.x); v.y = tf32f(v.y);
            v.z = tf32f(v.z); v.w = tf32f(v.w);
            dst[i] = v;
        }
    }
}

// ============================================================
// GEMM body (pre-rounded inputs, raw staging) — proven at R16
// ============================================================
template <bool RND>
__device__ __forceinline__ void gemm_body(const float* __restrict__ A,
                                          const float* __restrict__ W,
                                          const float* __restrict__ bias,
                                          float* __restrict__ C,
                                          int M, int N, int K, int m0, int n0) {
    __shared__ __align__(16) uint32_t sA[2][2 * (8 * 128 + 8)];
    __shared__ __align__(16) uint32_t sB[2][2 * (132 * 8 + 8)];
    const int tid = threadIdx.x;
    const int lrow = tid >> 1, oct = tid & 1, lk = oct * 8;
    const int lane = tid & 31, wid = tid >> 5;
    const int rb0 = (wid >> 1) * 2, nB = (wid & 1) * 64;
    const int gid = lane >> 2, tig = lane & 3;

    float acc[2][8][4];
#pragma unroll
    for (int i = 0; i < 2; i++)
#pragma unroll
        for (int j = 0; j < 8; j++)
#pragma unroll
            for (int c = 0; c < 4; c++) acc[i][j][c] = 0.f;

    const bool av = (m0 + lrow) < M, wv = (n0 + lrow) < N;
    const float* Ar = A + (size_t)(m0 + lrow) * K + lk;
    const float* Wr = W + (size_t)(n0 + lrow) * K + lk;
    float fA[8], fB[8];
    ld8(Ar, av, fA);
    ld8(Wr, wv, fB);
    storeA_raw<8>(sA[0], oct, lrow, fA);
    storeB_raw<132>(sB[0], oct, lrow, fB);
    __syncthreads();

    const int nk = K / 16;
    for (int kt = 0; kt < nk; kt++) {
        const int cur = kt & 1;
        const bool more = (kt + 1) < nk;
        if (more) {
            ld8(Ar + (kt + 1) * 16, av, fA);
            ld8(Wr + (kt + 1) * 16, wv, fB);
        }
#pragma unroll
        for (int o = 0; o < 2; o++) {
            uint4 a0 = loadA<8>(sA[cur], o, rb0, gid, tig);
            uint4 a1 = loadA<8>(sA[cur], o, rb0 + 1, gid, tig);
#pragma unroll
            for (int nt = 0; nt < 8; nt++) {
                uint2 bv = loadB<132>(sB[cur], o, tig, nB + nt * 8 + gid);
                mma_p(acc[0][nt], a0, bv);
                mma_p(acc[1][nt], a1, bv);
            }
        }
        if (more) {
            storeA_raw<8>(sA[cur ^ 1], oct, lrow, fA);
            storeB_raw<132>(sB[cur ^ 1], oct, lrow, fB);
            __syncthreads();
        }
    }

#pragma unroll
    for (int mt = 0; mt < 2; mt++) {
        int r = m0 + (rb0 + mt) * 16 + gid;
#pragma unroll
        for (int nt = 0; nt < 8; nt++) {
            int c = n0 + nB + nt * 8 + 2 * tig;
            float b0v = bias ? bias[c] : 0.f;
            float b1v = bias ? bias[c + 1] : 0.f;
            float v00 = acc[mt][nt][0] + b0v, v01 = acc[mt][nt][1] + b1v;
            float v10 = acc[mt][nt][2] + b0v, v11 = acc[mt][nt][3] + b1v;
            if (RND) {
                v00 = tf32f(v00); v01 = tf32f(v01);
                v10 = tf32f(v10); v11 = tf32f(v11);
            }
            if (r < M)
                *(float2*)(C + (size_t)r * N + c) = make_float2(v00, v01);
            if (r + 8 < M)
                *(float2*)(C + (size_t)(r + 8) * N + c) = make_float2(v10, v11);
        }
    }
}

__global__ __launch_bounds__(256, 2) void gemm_out(
    const float* __restrict__ A, const float* __restrict__ W,
    const float* __restrict__ bias, float* __restrict__ C, int M, int N, int K) {
    gemm_body<false>(A, W, bias, C, M, N, K, blockIdx.y * 128, blockIdx.x * 128);
}

__global__ __launch_bounds__(256, 2) void gemm_qkvp(
    const float* __restrict__ A, const float* __restrict__ rpe,
    const float* __restrict__ Wq, const float* __restrict__ Wk, const float* __restrict__ Wv,
    const float* __restrict__ Wp,
    const float* __restrict__ bq, const float* __restrict__ bk, const float* __restrict__ bv,
    float* __restrict__ Cq, float* __restrict__ Ck, float* __restrict__ Cv,
    float* __restrict__ Cp) {
    const int sel = blockIdx.x >> 3;
    if (sel == 3) {
        if (blockIdx.y >= 16) return;
        gemm_body<true>(rpe, Wp, nullptr, Cp, Lc, Dc, Dc,
                        blockIdx.y * 128, (blockIdx.x & 7) * 128);
        return;
    }
    const float* W = (sel == 0) ? Wq : (sel == 1) ? Wk : Wv;
    const float* bias = (sel == 0) ? bq : (sel == 1) ? bk : bv;
    float* C = (sel == 0) ? Cq : (sel == 1) ? Ck : Cv;
    gemm_body<true>(A, W, bias, C, Bc * Tc, Dc, Dc,
                    blockIdx.y * 128, (blockIdx.x & 7) * 128);
}

// ============================================================
// FUSED attention — 512 thr, cp.async 4-stage staging (no reg round-trip).
// smem (u32): Sb 32*1028 | Au 2112 | Av 2112 | 4 x 4864 bufs | mx 32 | inv 32
// phases 1/2: buf rows = n (K/P row), stride 76; phase 4: rows = k (V row), stride 72.
// ============================================================
#define SB_STR 1028
#define AU_OFF (32 * SB_STR)
#define AV_OFF (AU_OFF + 2112)
#define BF_OFF (AV_OFF + 2112)
#define BUF_STR 4864
#define MX_OFF (BF_OFF + 4 * BUF_STR)
#define INV_OFF (MX_OFF + 32)
#define FUSED_SMEM_BYTES ((INV_OFF + 32) * 4)

__global__ __launch_bounds__(512, 1) void fused_attn(
    const float* __restrict__ Q, const float* __restrict__ K,
    const float* __restrict__ P, const float* __restrict__ V,
    const float* __restrict__ u, const float* __restrict__ vb,
    float* __restrict__ probs, float* __restrict__ ctx) {
    extern __shared__ __align__(16) uint32_t su[];
    float* Sb = (float*)su;
    uint32_t* Au = su + AU_OFF;
    uint32_t* Av = su + AV_OFF;
    float* Bf = (float*)(su + BF_OFF);
    float* mx_s = (float*)(su + MX_OFF);
    float* inv_s = (float*)(su + INV_OFF);
    const uint32_t bfAddr = (uint32_t)__cvta_generic_to_shared(Bf);

    const int t = threadIdx.x;
    const int bh = blockIdx.y, zb = bh >> 4, h = bh & 15;
    const int q0 = blockIdx.x * 32;
    const int lane = t & 31, w = t >> 5;
    const int mB = (w & 1) * 16, rbw = w & 1, nBf = (w >> 1) * 8;
    const int gid = lane >> 2, tig = lane & 3;
    const int cidx = nBf + gid;

    // staging chunk coords: rows r0 and r0+32, 16B column c0
    const int r0 = t >> 4, c0 = (t & 15) * 4;
    const int hoff = h * HSc;

    // ---- stage q+u (t<256) / q+v (t>=256) as packed A fragments ----
    {
        int tt = t & 255;
        int qr = tt >> 3, o = tt & 7;
        const float* qp = Q + ((size_t)(zb * Tc) + q0 + qr) * Dc + hoff + o * 8;
        float a[8], bb[8];
        ld8(qp, true, a);
        if (t < 256) {
            ld8(u + hoff + o * 8, true, bb);
#pragma unroll
            for (int i = 0; i < 8; i++) bb[i] += a[i];
            storeA<2>(Au, o, qr, bb);
        } else {
            ld8(vb + hoff + o * 8, true, bb);
#pragma unroll
            for (int i = 0; i < 8; i++) bb[i] += a[i];
            storeA<2>(Av, o, qr, bb);
        }
    }

    uint4 aF[8];

    // ================= phase 1: ac = (q+u) K^T =================
    // stage K strip s into buf[s&3]: rows = K rows (n), stride 76
    {
        const float* kb = K + ((size_t)(zb * Tc) + r0) * Dc + hoff + c0;
#pragma unroll
        for (int s = 0; s < 3; s++) {
            uint32_t d = bfAddr + ((s & 3) * BUF_STR + r0 * 76 + c0) * 4;
            const float* src = kb + (size_t)(s * 64) * Dc;
            cpa16(d, src, 16);
            cpa16(d + 32 * 76 * 4, src + (size_t)32 * Dc, 16);
            CP_COMMIT();
        }
    }
    __syncthreads();   // A fragments staged
#pragma unroll
    for (int o = 0; o < 8; o++) aF[o] = loadA<2>(Au, o, rbw, gid, tig);

    for (int s = 0; s < 16; s++) {
        CP_WAIT2();
        __syncthreads();
        if (s + 3 < 16) {
            uint32_t d = bfAddr + (((s + 3) & 3) * BUF_STR + r0 * 76 + c0) * 4;
            const float* src =
                K + ((size_t)(zb * Tc) + (s + 3) * 64 + r0) * Dc + hoff + c0;
            cpa16(d, src, 16);
            cpa16(d + 32 * 76 * 4, src + (size_t)32 * Dc, 16);
        }
        CP_COMMIT();

        const float* bufF = Bf + (s & 3) * BUF_STR;
        float acc[4] = {0.f, 0.f, 0.f, 0.f};
#pragma unroll
        for (int o = 0; o < 8; o++) {
            int k = o * 8 + tig;
            uint2 b;
            b.x = __float_as_uint(bufF[cidx * 76 + k]);
            b.y = __float_as_uint(bufF[cidx * 76 + k + 4]);
            mma_p(acc, aF[o], b);
        }
        int col = s * 64 + nBf + 2 * tig;
        *(float2*)&Sb[(mB + gid) * SB_STR + col] = make_float2(acc[0], acc[1]);
        *(float2*)&Sb[(mB + gid + 8) * SB_STR + col] = make_float2(acc[2], acc[3]);
    }

    // ================= phase 2: bd band, scatter-add =================
    const int lStart = (Tc - 1) - (q0 + 31);
#pragma unroll
    for (int o = 0; o < 8; o++) aF[o] = loadA<2>(Av, o, rbw, gid, tig);
    {
#pragma unroll
        for (int s = 0; s < 3; s++) {
            int la = lStart + s * 64 + r0, lb = la + 32;
            uint32_t d = bfAddr + ((s & 3) * BUF_STR + r0 * 76 + c0) * 4;
            cpa16(d, P + (size_t)min(la, Lc - 1) * Dc + hoff + c0, la < Lc ? 16 : 0);
            cpa16(d + 32 * 76 * 4, P + (size_t)min(lb, Lc - 1) * Dc + hoff + c0,
                  lb < Lc ? 16 : 0);
            CP_COMMIT();
        }
    }
    for (int s = 0; s < 17; s++) {
        int lBase = lStart + s * 64;
        CP_WAIT2();
        __syncthreads();
        if (s + 3 < 17) {
            int la = lStart + (s + 3) * 64 + r0, lb = la + 32;
            uint32_t d = bfAddr + (((s + 3) & 3) * BUF_STR + r0 * 76 + c0) * 4;
            cpa16(d, P + (size_t)min(la, Lc - 1) * Dc + hoff + c0, la < Lc ? 16 : 0);
            cpa16(d + 32 * 76 * 4, P + (size_t)min(lb, Lc - 1) * Dc + hoff + c0,
                  lb < Lc ? 16 : 0);
        }
        CP_COMMIT();

        const float* bufF = Bf + (s & 3) * BUF_STR;
        float acc[4] = {0.f, 0.f, 0.f, 0.f};
#pragma unroll
        for (int o = 0; o < 8; o++) {
            int k = o * 8 + tig;
            uint2 b;
            b.x = __float_as_uint(bufF[cidx * 76 + k]);
            b.y = __float_as_uint(bufF[cidx * 76 + k + 4]);
            mma_p(acc, aF[o], b);
        }
        int lc = lBase + nBf + 2 * tig;
        int m = mB + gid;
        int j = (q0 + m) + lc - (Tc - 1);
        if (j >= 0 && j < Tc) Sb[m * SB_STR + j] += acc[0];
        if (j + 1 >= 0 && j + 1 < Tc) Sb[m * SB_STR + j + 1] += acc[1];
        int j2 = j + 8;
        if (j2 >= 0 && j2 < Tc) Sb[(m + 8) * SB_STR + j2] += acc[2];
        if (j2 + 1 >= 0 && j2 + 1 < Tc) Sb[(m + 8) * SB_STR + j2 + 1] += acc[3];
    }
    __syncthreads();

    // ===== phase 3a: row max (2 rows/warp) =====
#pragma unroll
    for (int rr = 0; rr < 2; rr++) {
        int row_i = w * 2 + rr;
        const float* row = Sb + row_i * SB_STR;
        float mx = -3.4e38f;
        for (int c = lane; c < Tc; c += 32) mx = fmaxf(mx, row[c]);
#pragma unroll
        for (int o = 16; o; o >>= 1) mx = fmaxf(mx, __shfl_xor_sync(0xffffffffu, mx, o));
        if (lane == 0) mx_s[row_i] = mx;
    }
    __syncthreads();

    // ===== phase 4: exp (FMA) + ctx; V staged rows = k, stride 72 =====
    const int row_e = t >> 4;
    const int ce = (t & 15) * 4;
    const float mxc = mx_s[row_e] * EXP_SCALE;
    float psum = 0.f;
    float* erow = Sb + row_e * SB_STR;

    {   // exp strip 0
        float4 x0 = *(float4*)&erow[ce];
        x0.x = fexp2(fmaf(x0.x, EXP_SCALE, -mxc)); x0.y = fexp2(fmaf(x0.y, EXP_SCALE, -mxc));
        x0.z = fexp2(fmaf(x0.z, EXP_SCALE, -mxc)); x0.w = fexp2(fmaf(x0.w, EXP_SCALE, -mxc));
        *(float4*)&erow[ce] = x0;
        psum += x0.x + x0.y + x0.z + x0.w;
    }

    float acc2[4] = {0.f, 0.f, 0.f, 0.f};
    {
        const float* vbp = V + ((size_t)(zb * Tc) + r0) * Dc + hoff + c0;
#pragma unroll
        for (int s = 0; s < 3; s++) {
            uint32_t d = bfAddr + ((s & 3) * BUF_STR + r0 * 72 + c0) * 4;
            const float* src = vbp + (size_t)(s * 64) * Dc;
            cpa16(d, src, 16);
            cpa16(d + 32 * 72 * 4, src + (size_t)32 * Dc, 16);
            CP_COMMIT();
        }
    }
    for (int s = 0; s < 16; s++) {
        CP_WAIT2();
        __syncthreads();
        if (s + 3 < 16) {
            uint32_t d = bfAddr + (((s + 3) & 3) * BUF_STR + r0 * 72 + c0) * 4;
            const float* src =
                V + ((size_t)(zb * Tc) + (s + 3) * 64 + r0) * Dc + hoff + c0;
            cpa16(d, src, 16);
            cpa16(d + 32 * 72 * 4, src + (size_t)32 * Dc, 16);
        }
        CP_COMMIT();
        if (s + 1 < 16) {
            float* ep = erow + (s + 1) * 64 + ce;
            float4 x0 = *(float4*)ep;
            x0.x = fexp2(fmaf(x0.x, EXP_SCALE, -mxc)); x0.y = fexp2(fmaf(x0.y, EXP_SCALE, -mxc));
            x0.z = fexp2(fmaf(x0.z, EXP_SCALE, -mxc)); x0.w = fexp2(fmaf(x0.w, EXP_SCALE, -mxc));
            *(float4*)ep = x0;
            psum += x0.x + x0.y + x0.z + x0.w;
        }

        const float* Vtc = Bf + (s & 3) * BUF_STR;
        const float* ar0 = Sb + (mB + gid) * SB_STR + s * 64;
        const float* ar8 = ar0 + 8 * SB_STR;
#pragma unroll
        for (int o = 0; o < 8; o++) {
            uint4 a;
            a.x = tf32_of(ar0[o * 8 + tig]);
            a.y = tf32_of(ar8[o * 8 + tig]);
            a.z = tf32_of(ar0[o * 8 + tig + 4]);
            a.w = tf32_of(ar8[o * 8 + tig + 4]);
            int k = o * 8 + tig;
            uint2 b;
            b.x = __float_as_uint(Vtc[k * 72 + cidx]);
            b.y = __float_as_uint(Vtc[(k + 4) * 72 + cidx]);
            mma_p(acc2, a, b);
        }
    }

    // ---- row-sum reduce over 16 lanes sharing a row ----
#pragma unroll
    for (int o = 8; o; o >>= 1) psum += __shfl_xor_sync(0xffffffffu, psum, o);
    if ((lane & 15) == 0) inv_s[row_e] = 1.f / psum;
    __syncthreads();

    // ---- write probs = e * inv ----
    {
        float* pb = probs + ((size_t)bh << 20) + (size_t)q0 * Tc;
#pragma unroll 4
        for (int it = 0; it < 16; it++) {
            int idx = it * 512 + t;
            int r = idx >> 8, c4 = (idx & 255) * 4;
            float iv = inv_s[r];
            float4 val = *(float4*)&Sb[r * SB_STR + c4];
            val.x *= iv; val.y *= iv; val.z *= iv; val.w *= iv;
            *(float4*)(pb + (size_t)r * Tc + c4) = val;
        }
    }

    // ---- ctx epilogue: scale by inv, rounded (out-GEMM stages raw) ----
    {
        int r = q0 + mB + gid;
        float iv0 = inv_s[mB + gid], iv8 = inv_s[mB + gid + 8];
        int c = nBf + 2 * tig;
        *(float2*)(ctx + ((size_t)(zb * Tc) + r) * Dc + hoff + c) =
            make_float2(tf32f(acc2[0] * iv0), tf32f(acc2[1] * iv0));
        *(float2*)(ctx + ((size_t)(zb * Tc) + r + 8) * Dc + hoff + c) =
            make_float2(tf32f(acc2[2] * iv8), tf32f(acc2[3] * iv8));
    }
}

// ============================================================
extern "C" void kernel_launch(void* const* d_in, const int* in_sizes, int n_in,
                              void* d_out, int out_size) {
    const float* hs  = (const float*)d_in[0];
    const float* rpe = (const float*)d_in[1];
    const float* Wq  = (const float*)d_in[2];
    const float* bq  = (const float*)d_in[3];
    const float* Wk  = (const float*)d_in[4];
    const float* bk  = (const float*)d_in[5];
    const float* Wv  = (const float*)d_in[6];
    const float* bv  = (const float*)d_in[7];
    const float* Wo  = (const float*)d_in[8];
    const float* bo  = (const float*)d_in[9];
    const float* Wp  = (const float*)d_in[10];
    const float* pu  = (const float*)d_in[11];
    const float* pvb = (const float*)d_in[12];

    float* out = (float*)d_out;
    float* S   = out + (size_t)Bc * Tc * Dc;

    float *pq, *pk, *pv, *pp, *pctx;
    float *hsr, *rper, *wq, *wk, *wv, *wp, *wo;
    cudaGetSymbolAddress((void**)&pq,   g_q);
    cudaGetSymbolAddress((void**)&pk,   g_k);
    cudaGetSymbolAddress((void**)&pv,   g_v);
    cudaGetSymbolAddress((void**)&pp,   g_p);
    cudaGetSymbolAddress((void**)&pctx, g_ctx);
    cudaGetSymbolAddress((void**)&hsr,  g_hsr);
    cudaGetSymbolAddress((void**)&rper, g_rper);
    cudaGetSymbolAddress((void**)&wq,   g_wq);
    cudaGetSymbolAddress((void**)&wk,   g_wk);
    cudaGetSymbolAddress((void**)&wv,   g_wv);
    cudaGetSymbolAddress((void**)&wp,   g_wp);
    cudaGetSymbolAddress((void**)&wo,   g_wo);

    cudaFuncSetAttribute(fused_attn, cudaFuncAttributeMaxDynamicSharedMemorySize,
                         FUSED_SMEM_BYTES);

    RArgs ra;
    ra.src[0] = hs;  ra.dst[0] = hsr;  ra.n4[0] = (Bc * Tc * Dc) / 4;
    ra.src[1] = rpe; ra.dst[1] = rper; ra.n4[1] = (Lc * Dc) / 4;
    ra.src[2] = Wq;  ra.dst[2] = wq;   ra.n4[2] = (Dc * Dc) / 4;
    ra.src[3] = Wk;  ra.dst[3] = wk;   ra.n4[3] = (Dc * Dc) / 4;
    ra.src[4] = Wv;  ra.dst[4] = wv;   ra.n4[4] = (Dc * Dc) / 4;
    ra.src[5] = Wp;  ra.dst[5] = wp;   ra.n4[5] = (Dc * Dc) / 4;
    ra.src[6] = Wo;  ra.dst[6] = wo;   ra.n4[6] = (Dc * Dc) / 4;
    round_all<<<1024, 256>>>(ra);

    gemm_qkvp<<<dim3(32, 32), 256>>>(hsr, rper, wq, wk, wv, wp, bq, bk, bv,
                                     pq, pk, pv, pp);

    fused_attn<<<dim3(Tc / 32, Bc * Hc), 512, FUSED_SMEM_BYTES>>>(
        pq, pk, pp, pv, pu, pvb, S, pctx);

    gemm_out<<<dim3(8, 32), 256>>>(pctx, wo, bo, out, Bc * Tc, Dc, Dc);
}